// round 8
// baseline (speedup 1.0000x reference)
#include <cuda_runtime.h>
#include <math.h>

constexpr int NN = 307, TT = 12, BB = 32, EE = 10;
constexpr int MT = TT * BB;   // 384
constexpr int BN = BB * NN;   // 9824

// ---------------- f32x2 helpers ----------------
typedef unsigned long long ull;
__device__ __forceinline__ ull pk2(float x) {
    ull r; asm("mov.b64 %0, {%1, %1};" : "=l"(r) : "f"(x)); return r;
}
__device__ __forceinline__ ull pk(float a, float b) {
    ull r; asm("mov.b64 %0, {%1, %2};" : "=l"(r) : "f"(a), "f"(b)); return r;
}
__device__ __forceinline__ void ffma2(ull& d, ull a, ull b) {
    asm("fma.rn.f32x2 %0, %1, %2, %0;" : "+l"(d) : "l"(a), "l"(b));
}
__device__ __forceinline__ void unpk(ull v, float& a, float& b) {
    asm("mov.b64 {%0, %1}, %2;" : "=f"(a), "=f"(b) : "l"(v));
}

// ---------------- scratch arena (ALL offsets 16B-aligned) ----------------
constexpr size_t AL(size_t x) { return (x + 3) & ~(size_t)3; }

constexpr size_t S_A  = (size_t)NN * NN;
constexpr size_t S_WH = (size_t)NN * 128 * 128;
constexpr size_t S_WU = (size_t)NN * 128 * 64;
constexpr size_t S_BG = (size_t)NN * 128;
constexpr size_t S_BU = (size_t)NN * 64;
constexpr size_t S_XG = (size_t)MT * NN * 128;
constexpr size_t S_XU = (size_t)MT * NN * 64;
constexpr size_t S_HS = (size_t)MT * NN * 64;
constexpr size_t S_HB = (size_t)BB * NN * 64;

constexpr size_t O_A    = 0;
constexpr size_t O_ATR  = AL(O_A    + S_A);
constexpr size_t O_WHG0 = AL(O_ATR  + S_A);
constexpr size_t O_WHU0 = AL(O_WHG0 + S_WH);
constexpr size_t O_WXG0 = AL(O_WHU0 + S_WU);
constexpr size_t O_WXU0 = AL(O_WXG0 + (size_t)NN * 2 * 128);
constexpr size_t O_WHG1 = AL(O_WXU0 + (size_t)NN * 2 * 64);
constexpr size_t O_WHU1 = AL(O_WHG1 + S_WH);
constexpr size_t O_WXG1 = AL(O_WHU1 + S_WU);
constexpr size_t O_WXU1 = AL(O_WXG1 + S_WH);
constexpr size_t O_BG0  = AL(O_WXU1 + S_WU);
constexpr size_t O_BU0  = AL(O_BG0  + S_BG);
constexpr size_t O_BG1  = AL(O_BU0  + S_BU);
constexpr size_t O_BU1  = AL(O_BG1  + S_BG);
constexpr size_t O_AX0  = AL(O_BU1  + S_BU);
constexpr size_t O_XCG0 = AL(O_AX0  + (size_t)MT * NN);
constexpr size_t O_XCU0 = AL(O_XCG0 + S_XG);
constexpr size_t O_XCG1 = AL(O_XCU0 + S_XU);
constexpr size_t O_XCU1 = AL(O_XCG1 + S_XG);
constexpr size_t O_HS0  = AL(O_XCU1 + S_XU);
constexpr size_t O_AX1  = AL(O_HS0  + S_HS);
constexpr size_t O_H    = AL(O_AX1  + S_HS);
constexpr size_t O_AH   = AL(O_H    + S_HB);
constexpr size_t O_ZH   = AL(O_AH   + S_HB);
constexpr size_t O_AZH  = AL(O_ZH   + S_HB);
constexpr size_t O_R    = AL(O_AZH  + S_HB);
constexpr size_t O_O1   = AL(O_R    + S_HB);
constexpr size_t O_TBL  = AL(O_O1   + S_HB);
constexpr size_t TOTAL  = O_TBL  + 2048;

__device__ __align__(16) float g_mem[TOTAL];
__device__ unsigned int g_bar;

// ---------------- software grid barrier (persistent kernel) ----------------
// __threadfence() is gpu-scope -> emits CCTL.IVALL on sm_103a: flushes/invalidates
// L1D, so plain loads after the barrier see other SMs' plain stores.
__device__ __forceinline__ void grid_sync(unsigned int target) {
    __threadfence();
    __syncthreads();
    if (threadIdx.x == 0) {
        atomicAdd(&g_bar, 1u);
        while (*(volatile unsigned int*)&g_bar < target) __nanosleep(64);
    }
    __syncthreads();
    __threadfence();
}

// ---------------- adjacency ----------------
__global__ void adj_kernel(const float* __restrict__ ne, float* __restrict__ A,
                           float* __restrict__ AT) {
    int n = blockIdx.x, tid = threadIdx.x;
    __shared__ float nen[EE];
    __shared__ float rowv[NN];
    __shared__ float red[4];
    if (tid < EE) nen[tid] = ne[n * EE + tid];
    __syncthreads();
    float lmax = -1e30f;
    for (int m = tid; m < NN; m += 128) {
        float d = 0.f;
#pragma unroll
        for (int e = 0; e < EE; e++) d += nen[e] * ne[m * EE + e];
        d = fmaxf(d, 0.f);
        rowv[m] = d;
        lmax = fmaxf(lmax, d);
    }
    for (int o = 16; o; o >>= 1) lmax = fmaxf(lmax, __shfl_xor_sync(~0u, lmax, o));
    if ((tid & 31) == 0) red[tid >> 5] = lmax;
    __syncthreads();
    float bmax = fmaxf(fmaxf(red[0], red[1]), fmaxf(red[2], red[3]));
    float lsum = 0.f;
    for (int m = tid; m < NN; m += 128) {
        float e = expf(rowv[m] - bmax);
        rowv[m] = e;
        lsum += e;
    }
    for (int o = 16; o; o >>= 1) lsum += __shfl_xor_sync(~0u, lsum, o);
    __syncthreads();
    if ((tid & 31) == 0) red[tid >> 5] = lsum;
    __syncthreads();
    float inv = 1.f / (red[0] + red[1] + red[2] + red[3]);
    for (int m = tid; m < NN; m += 128) {
        float v = rowv[m] * inv;
        A[(size_t)n * NN + m]  = v;
        AT[(size_t)m * NN + n] = v;
    }
}

// ---------------- per-node weight/bias mixing ----------------
__global__ void wmix_kernel(const float* __restrict__ ne, const float* __restrict__ src,
                            float* __restrict__ dst, int R, int O, int Isrc, int ioff,
                            int rdiv, int total) {
    int idx = blockIdx.x * blockDim.x + threadIdx.x;
    if (idx >= total) return;
    int o = idx % O;
    int r = (idx / O) % R;
    int n = idx / (O * R);
    int k = r / rdiv;
    int i = ioff + (r % rdiv);
    float acc = 0.f;
#pragma unroll
    for (int e = 0; e < EE; e++)
        acc += ne[n * EE + e] * src[(((size_t)e * 2 + k) * Isrc + i) * O + o];
    dst[idx] = acc;
}

__global__ void bmix_kernel(const float* __restrict__ ne, const float* __restrict__ src,
                            float* __restrict__ dst, int O, int total) {
    int idx = blockIdx.x * blockDim.x + threadIdx.x;
    if (idx >= total) return;
    int o = idx % O, n = idx / O;
    float acc = 0.f;
#pragma unroll
    for (int e = 0; e < EE; e++) acc += ne[n * EE + e] * src[e * O + o];
    dst[idx] = acc;
}

// ---------------- ax0[m][n] = sum_mm A[n][mm]*src[b,t,mm], m=t*32+b ----------------
__global__ void ax0_kernel(const float* __restrict__ AT, const float* __restrict__ src,
                           float* __restrict__ ax0) {
    int m = blockIdx.x;
    int b = m & 31, t = m >> 5;
    __shared__ float ss[NN];
    int tid = threadIdx.x;  // 320
    if (tid < NN) ss[tid] = src[((size_t)b * TT + t) * NN + tid];
    __syncthreads();
    if (tid < NN) {
        float acc = 0.f;
        for (int mm = 0; mm < NN; mm++) acc += AT[(size_t)mm * NN + tid] * ss[mm];
        ax0[(size_t)m * NN + tid] = acc;
    }
}

// ---------------- layer-0 x-contribution ----------------
template <int O>
__global__ void xc0_kernel(const float* __restrict__ src, const float* __restrict__ ax0,
                           const float* __restrict__ Wx, const float* __restrict__ Bv,
                           float* __restrict__ xc) {
    size_t idx = (size_t)blockIdx.x * blockDim.x + threadIdx.x;
    if (idx >= (size_t)MT * NN * O) return;
    int o = (int)(idx % O);
    int n = (int)((idx / O) % NN);
    int m = (int)(idx / ((size_t)O * NN));
    int b = m & 31, t = m >> 5;
    float s = src[((size_t)b * TT + t) * NN + n];
    float a = ax0[(size_t)m * NN + n];
    xc[idx] = s * Wx[((size_t)n * 2) * O + o] + a * Wx[((size_t)n * 2 + 1) * O + o]
            + Bv[(size_t)n * O + o];
}

// ---------------- t=0 specialized step ----------------
__global__ void step0_kernel(const float* __restrict__ XCG, const float* __restrict__ XCU,
                             float* __restrict__ H, float* __restrict__ HS) {
    int idx = blockIdx.x * blockDim.x + threadIdx.x;
    if (idx >= BB * NN * 64) return;
    int ib = idx >> 6, o = idx & 63;
    float r = 1.f / (1.f + expf(-XCG[(size_t)ib * 128 + 64 + o]));
    float hc = tanhf(XCU[idx]);
    float h = (1.f - r) * hc;
    H[idx] = h;
    HS[idx] = h;
}

// ---------------- A @ V job (32-node tile x one batch) ----------------
// sm layout: vs = sm[0..2047] (32x64), as_ = sm[2048..3135] (32x34)
__device__ __forceinline__ void av_job(const float* __restrict__ A,
                                       const float* __restrict__ V,
                                       float* __restrict__ OUT,
                                       int job, float* sm) {
    __syncthreads();   // smem reuse guard (jobs/phases share sm)
    int n0 = (job % 10) * 32, bb = job / 10;
    const float* Vb = V + (size_t)bb * NN * 64;
    float* Ob = OUT + (size_t)bb * NN * 64;
    float* vs = sm;
    float* as_ = sm + 2048;
    int tid = threadIdx.x, tx = tid & 31, ty = tid >> 5;
    ull acc[2][2] = {{0ull, 0ull}, {0ull, 0ull}};
    float4 vreg[2]; float areg[4];
    auto ldtile = [&](int m0, float4 vr[2], float ar[4]) {
#pragma unroll
        for (int s = 0; s < 2; s++) {
            int q = tid + s * 256;
            int mm = q >> 4, c4 = (q & 15) * 4;
            int m = m0 + mm;
            vr[s] = (m < NN) ? *reinterpret_cast<const float4*>(&Vb[(size_t)m * 64 + c4])
                             : make_float4(0.f, 0.f, 0.f, 0.f);
        }
#pragma unroll
        for (int s = 0; s < 4; s++) {
            int i = tid + s * 256;
            int mm = i & 31, j = i >> 5;
            int m = m0 + mm, n2 = n0 + j;
            ar[s] = (m < NN && n2 < NN) ? A[(size_t)n2 * NN + m] : 0.f;
        }
    };
    ldtile(0, vreg, areg);
#pragma unroll 1
    for (int t = 0; t < 10; t++) {
        if (t) __syncthreads();
#pragma unroll
        for (int s = 0; s < 2; s++) {
            int q = tid + s * 256;
            *reinterpret_cast<float4*>(&vs[(q >> 4) * 64 + (q & 15) * 4]) = vreg[s];
        }
#pragma unroll
        for (int s = 0; s < 4; s++) {
            int i = tid + s * 256;
            as_[(i & 31) * 34 + (i >> 5)] = areg[s];
        }
        __syncthreads();
        if (t < 9) ldtile((t + 1) * 32, vreg, areg);
#pragma unroll
        for (int mm = 0; mm < 32; mm++) {
            ull a01 = *reinterpret_cast<const ull*>(&as_[mm * 34 + 4 * ty]);
            ull a23 = *reinterpret_cast<const ull*>(&as_[mm * 34 + 4 * ty + 2]);
            ull v0 = pk2(vs[mm * 64 + tx]);
            ull v1 = pk2(vs[mm * 64 + tx + 32]);
            ffma2(acc[0][0], a01, v0);
            ffma2(acc[1][0], a23, v0);
            ffma2(acc[0][1], a01, v1);
            ffma2(acc[1][1], a23, v1);
        }
    }
    int nb = n0 + 4 * ty;
    float o00, o01, o10, o11, o20, o21, o30, o31;
    unpk(acc[0][0], o00, o10);
    unpk(acc[1][0], o20, o30);
    unpk(acc[0][1], o01, o11);
    unpk(acc[1][1], o21, o31);
    if (nb < NN)     { Ob[(size_t)nb * 64 + tx] = o00;       Ob[(size_t)nb * 64 + tx + 32] = o01; }
    if (nb + 1 < NN) { Ob[(size_t)(nb+1) * 64 + tx] = o10;   Ob[(size_t)(nb+1) * 64 + tx + 32] = o11; }
    if (nb + 2 < NN) { Ob[(size_t)(nb+2) * 64 + tx] = o20;   Ob[(size_t)(nb+2) * 64 + tx + 32] = o21; }
    if (nb + 3 < NN) { Ob[(size_t)(nb+3) * 64 + tx] = o30;   Ob[(size_t)(nb+3) * 64 + tx + 32] = o31; }
}

// ---------------- per-node GEMM job ----------------
// sm layout: xs = sm[0..4095] (32x128), ws = sm[4096..4096+32*O)
template <int O, int MODE>
__device__ __forceinline__ void gemm_job(
        int n, int m0,
        const float* __restrict__ X1, const float* __restrict__ X2,
        const float* __restrict__ W, const float* __restrict__ AX,
        const float* __restrict__ RB, const float* __restrict__ HOLD,
        float* __restrict__ C, float* __restrict__ C2, float* sm) {
    constexpr int NP = O / 64;
    constexpr int WV = O / 32;
    __syncthreads();   // smem reuse guard
    float* xs = sm;
    float* ws = sm + 4096;
    int tid = threadIdx.x, tx = tid & 31, ty = tid >> 5;
#pragma unroll
    for (int s = 0; s < 4; s++) {
        int q = tid + s * 256;
        int m = q >> 5, j4 = (q & 31) * 4;
        const float* sp = (j4 < 64) ? X1 : X2;
        float4 v = *reinterpret_cast<const float4*>(
            &sp[((size_t)(m0 + m) * NN + n) * 64 + (j4 & 63)]);
        *reinterpret_cast<float4*>(&xs[m * 128 + j4]) = v;
    }
    const float* Wn = W + (size_t)n * 128 * O;
    float4 wst[WV];
#pragma unroll
    for (int s = 0; s < WV; s++)
        wst[s] = reinterpret_cast<const float4*>(Wn)[tid + s * 256];
    ull acc[4][NP];
#pragma unroll
    for (int r = 0; r < 4; r++)
#pragma unroll
        for (int p = 0; p < NP; p++) acc[r][p] = 0ull;
#pragma unroll 1
    for (int k0 = 0; k0 < 4; k0++) {
        if (k0) __syncthreads();
#pragma unroll
        for (int s = 0; s < WV; s++)
            reinterpret_cast<float4*>(ws)[tid + s * 256] = wst[s];
        __syncthreads();
        if (k0 < 3) {
            const float4* Wt = reinterpret_cast<const float4*>(Wn + (size_t)(k0 + 1) * 32 * O);
#pragma unroll
            for (int s = 0; s < WV; s++) wst[s] = Wt[tid + s * 256];
        }
#pragma unroll
        for (int kk = 0; kk < 32; kk++) {
            ull wp[NP];
#pragma unroll
            for (int p = 0; p < NP; p++)
                wp[p] = *reinterpret_cast<const ull*>(&ws[kk * O + 2 * tx + 64 * p]);
#pragma unroll
            for (int r = 0; r < 4; r++) {
                ull xp = pk2(xs[(ty + 8 * r) * 128 + k0 * 32 + kk]);
#pragma unroll
                for (int p = 0; p < NP; p++) ffma2(acc[r][p], xp, wp[p]);
            }
        }
    }
#pragma unroll
    for (int r = 0; r < 4; r++) {
        int m = m0 + ty + 8 * r;
        size_t ib = (size_t)m * NN + n;
#pragma unroll
        for (int p = 0; p < NP; p++) {
            float v0, v1;
            unpk(acc[r][p], v0, v1);
            int o0 = 2 * tx + 64 * p;
            if (MODE == 0) {
                C[ib * O + o0]     = v0 + AX[(size_t)n * O + o0];
                C[ib * O + o0 + 1] = v1 + AX[(size_t)n * O + o0 + 1];
            } else if (MODE == 1) {
                float s0 = 1.f / (1.f + expf(-(v0 + AX[ib * O + o0])));
                float s1 = 1.f / (1.f + expf(-(v1 + AX[ib * O + o0 + 1])));
                if (p == 0) {
                    C2[ib * 64 + o0]     = s0 * HOLD[ib * 64 + o0];
                    C2[ib * 64 + o0 + 1] = s1 * HOLD[ib * 64 + o0 + 1];
                } else {
                    C[ib * 64 + o0 - 64] = s0;
                    C[ib * 64 + o0 - 63] = s1;
                }
            } else {
                float hc0 = tanhf(v0 + AX[ib * O + o0]);
                float hc1 = tanhf(v1 + AX[ib * O + o0 + 1]);
                float r0 = RB[ib * 64 + o0], r1 = RB[ib * 64 + o0 + 1];
                float hd0 = HOLD[ib * 64 + o0], hd1 = HOLD[ib * 64 + o0 + 1];
                float h0 = r0 * hd0 + (1.f - r0) * hc0;
                float h1 = r1 * hd1 + (1.f - r1) * hc1;
                C[ib * 64 + o0] = h0;  C[ib * 64 + o0 + 1] = h1;
                if (C2) { C2[ib * 64 + o0] = h0; C2[ib * 64 + o0 + 1] = h1; }
            }
        }
    }
}

// ---------------- standalone wrappers (parallel precompute) ----------------
__global__ void __launch_bounds__(256) av_kernel(
        const float* __restrict__ A, const float* __restrict__ V,
        float* __restrict__ OUT) {
    __shared__ __align__(16) float sm[3136];
    av_job(A, V, OUT, blockIdx.y * 10 + blockIdx.x, sm);
}

template <int O, int MODE>
__global__ void __launch_bounds__(256) node_gemm(
        const float* __restrict__ X1, const float* __restrict__ X2,
        const float* __restrict__ W, const float* __restrict__ AX,
        const float* __restrict__ RB, const float* __restrict__ HOLD,
        float* __restrict__ C, float* __restrict__ C2) {
    __shared__ __align__(16) float sm[4096 + 32 * O];
    gemm_job<O, MODE>(blockIdx.x, blockIdx.y * 32, X1, X2, W, AX, RB, HOLD, C, C2, sm);
}

// ---------------- persistent GRU layer kernel ----------------
// 2 blocks/SM guaranteed: regs<=128 (launch_bounds), smem 32KB, 256 thr.
__global__ void __launch_bounds__(256, 2) gru_loop(
        const float* __restrict__ A, const float* __restrict__ WG,
        const float* __restrict__ WU, const float* __restrict__ XCG,
        const float* __restrict__ XCU,
        float* __restrict__ H, float* __restrict__ AH, float* __restrict__ ZH,
        float* __restrict__ AZH, float* __restrict__ R, float* __restrict__ HS) {
    __shared__ __align__(16) float sm[8192];
    unsigned int bar = 0;
#pragma unroll 1
    for (int t = 1; t < TT; t++) {
        const float* xcg = XCG + (size_t)t * BB * NN * 128;
        const float* xcu = XCU + (size_t)t * BB * NN * 64;
        float* hs = HS ? HS + (size_t)t * BB * NN * 64 : nullptr;
        for (int j = blockIdx.x; j < 320; j += gridDim.x)
            av_job(A, H, AH, j, sm);
        bar += gridDim.x; grid_sync(bar);
        for (int j = blockIdx.x; j < NN; j += gridDim.x)
            gemm_job<128, 1>(j, 0, H, AH, WG, xcg, nullptr, H, R, ZH, sm);
        bar += gridDim.x; grid_sync(bar);
        for (int j = blockIdx.x; j < 320; j += gridDim.x)
            av_job(A, ZH, AZH, j, sm);
        bar += gridDim.x; grid_sync(bar);
        for (int j = blockIdx.x; j < NN; j += gridDim.x)
            gemm_job<64, 2>(j, 0, ZH, AZH, WU, xcu, R, H, H, hs, sm);
        bar += gridDim.x; grid_sync(bar);
    }
}

// ---------------- attention tables ----------------
__global__ void attn_prep(const float* __restrict__ mw, const float* __restrict__ mb,
                          const float* __restrict__ wq, const float* __restrict__ bq,
                          const float* __restrict__ wk, const float* __restrict__ bk,
                          const float* __restrict__ wv, const float* __restrict__ bv,
                          float* __restrict__ tbl) {
    __shared__ float MQ[64], MK[64], CQ11[64], CK[12][64], CT[12][64];
    int o = threadIdx.x;  // 64 threads
    for (int t = 0; t < 12; t++) {
        int p = o >> 1;
        float ang = (float)t * powf(10000.f, -(float)(2 * p) / 64.f);
        CT[t][o] = mb[o] + ((o & 1) ? cosf(ang) : sinf(ang));
    }
    __syncthreads();
    float mq = 0.f, mk = 0.f, mv = 0.f;
    for (int i = 0; i < 64; i++) {
        float w = mw[i];
        mq += w * wq[i * 64 + o];
        mk += w * wk[i * 64 + o];
        mv += w * wv[i * 64 + o];
    }
    MQ[o] = mq; MK[o] = mk;
    tbl[o] = mv;
    tbl[64 + o] = CT[11][o];
    float cq = bq[o];
    for (int i = 0; i < 64; i++) cq += CT[11][i] * wq[i * 64 + o];
    CQ11[o] = cq;
    for (int t = 0; t < 12; t++) {
        float ck = bk[o], cv = bv[o];
        for (int i = 0; i < 64; i++) {
            float c = CT[t][i];
            ck += c * wk[i * 64 + o];
            cv += c * wv[i * 64 + o];
        }
        CK[t][o] = ck;
        tbl[128 + t * 64 + o] = cv;
    }
    __syncthreads();
    if (o < 4) {
        float a = 0.f, c = 0.f;
        for (int d = 0; d < 16; d++) {
            a += MQ[o * 16 + d] * MK[o * 16 + d];
            c += CQ11[o * 16 + d] * MK[o * 16 + d];
        }
        tbl[896 + o] = a;
        tbl[900 + o] = c;
    }
    if (o < 48) {
        int h = o / 12, s = o % 12;
        float b = 0.f, dd = 0.f;
        for (int d = 0; d < 16; d++) {
            b  += MQ[h * 16 + d] * CK[s][h * 16 + d];
            dd += CQ11[h * 16 + d] * CK[s][h * 16 + d];
        }
        tbl[904 + o] = b;
        tbl[952 + o] = dd;
    }
}

// ---------------- attention + wo + LN1 ----------------
__global__ void attn_main(const float* __restrict__ src, const float* __restrict__ mw,
                          const float* __restrict__ wo, const float* __restrict__ bo,
                          const float* __restrict__ g1, const float* __restrict__ b1,
                          const float* __restrict__ tblg, float* __restrict__ O1) {
    __shared__ float tbl[1000];
    __shared__ float wos[4096];
    __shared__ float ovs[64][65];
    int tid = threadIdx.x;
    for (int i = tid; i < 1000; i += 256) tbl[i] = tblg[i];
    for (int i = tid; i < 4096; i += 256) wos[i] = wo[i];
    __syncthreads();
    int g = tid >> 2, hq = tid & 3;
    int bn = blockIdx.x * 64 + g;
    bool act = bn < BN;
    int b = act ? bn / NN : 0;
    int n = act ? bn % NN : 0;
    float sv[12];
    for (int s = 0; s < 12; s++) sv[s] = src[((size_t)b * TT + s) * NN + n];
    float sT = sv[11];
    const float* Ah = tbl + 896;
    const float* Ch = tbl + 900;
    const float* Bh = tbl + 904;
    const float* Dh = tbl + 952;
    float sc[12], smax = -1e30f;
    for (int s = 0; s < 12; s++) {
        float v = 0.25f * (sT * sv[s] * Ah[hq] + sT * Bh[hq * 12 + s]
                           + sv[s] * Ch[hq] + Dh[hq * 12 + s]);
        sc[s] = v;
        smax = fmaxf(smax, v);
    }
    float ssum = 0.f;
    for (int s = 0; s < 12; s++) { sc[s] = expf(sc[s] - smax); ssum += sc[s]; }
    float inv = 1.f / ssum, sa = 0.f;
    for (int s = 0; s < 12; s++) { sc[s] *= inv; sa += sc[s] * sv[s]; }
    for (int d = 0; d < 16; d++) {
        int dg = hq * 16 + d;
        float ov = sa * tbl[dg];
        for (int s = 0; s < 12; s++) ov += sc[s] * tbl[128 + s * 64 + dg];
        ovs[g][dg] = ov;
    }
    __syncthreads();
    float u[16], lsum = 0.f, lsq = 0.f;
    for (int d = 0; d < 16; d++) {
        int o = hq * 16 + d;
        float acc = bo[o];
        for (int i = 0; i < 64; i++) acc += ovs[g][i] * wos[i * 64 + o];
        float uu = sT * mw[o] + tbl[64 + o] + acc;
        u[d] = uu;
        lsum += uu;
        lsq += uu * uu;
    }
    lsum += __shfl_xor_sync(~0u, lsum, 1); lsum += __shfl_xor_sync(~0u, lsum, 2);
    lsq  += __shfl_xor_sync(~0u, lsq, 1);  lsq  += __shfl_xor_sync(~0u, lsq, 2);
    float mean = lsum / 64.f, var = lsq / 64.f - mean * mean;
    float rs = rsqrtf(var + 1e-5f);
    if (act)
        for (int d = 0; d < 16; d++) {
            int o = hq * 16 + d;
            O1[(size_t)bn * 64 + o] = (u[d] - mean) * rs * g1[o] + b1[o];
        }
}

// ---------------- FFN + LN2 + combine + conv ----------------
__global__ void __launch_bounds__(256) ffn_kernel(
        const float* __restrict__ O1, const float* __restrict__ W1,
        const float* __restrict__ B1f, const float* __restrict__ W2,
        const float* __restrict__ B2f, const float* __restrict__ g2,
        const float* __restrict__ b2l, const float* __restrict__ HL,
        const float* __restrict__ wsp, const float* __restrict__ wtp,
        const float* __restrict__ cw, const float* __restrict__ cb,
        float* __restrict__ OUT) {
    __shared__ float xs[32][64];
    __shared__ float w1t[64][32];
    __shared__ float ht[32][33];
    __shared__ float w2t[32][64];
    int tid = threadIdx.x, tx = tid & 31, ty = tid >> 5;
    int m0 = blockIdx.x * 32;
    for (int i = tid; i < 2048; i += 256) {
        int a = i >> 6, c = i & 63;
        xs[a][c] = O1[(size_t)(m0 + a) * 64 + c];
    }
    ull acc[4] = {0ull, 0ull, 0ull, 0ull};
#pragma unroll 1
    for (int j0 = 0; j0 < 1024; j0 += 32) {
        __syncthreads();
        for (int i = tid; i < 2048; i += 256)
            w1t[i >> 5][i & 31] = W1[(size_t)(i >> 5) * 1024 + j0 + (i & 31)];
        for (int i = tid; i < 2048; i += 256)
            w2t[i >> 6][i & 63] = W2[(size_t)(j0 + (i >> 6)) * 64 + (i & 63)];
        __syncthreads();
#pragma unroll
        for (int rep = 0; rep < 2; rep++) {
            int slot = tid + rep * 256;
            int a = slot >> 4, bp = (slot & 15) * 2;
            ull h = pk(B1f[j0 + bp], B1f[j0 + bp + 1]);
#pragma unroll
            for (int k = 0; k < 64; k++)
                ffma2(h, pk2(xs[a][k]),
                      *reinterpret_cast<const ull*>(&w1t[k][bp]));
            float h0, h1;
            unpk(h, h0, h1);
            ht[a][bp]     = fmaxf(h0, 0.f);
            ht[a][bp + 1] = fmaxf(h1, 0.f);
        }
        __syncthreads();
#pragma unroll
        for (int jj = 0; jj < 32; jj++) {
            ull w = *reinterpret_cast<const ull*>(&w2t[jj][2 * tx]);
#pragma unroll
            for (int r = 0; r < 4; r++)
                ffma2(acc[r], pk2(ht[ty + 8 * r][jj]), w);
        }
    }
#pragma unroll
    for (int r = 0; r < 4; r++) {
        int row = m0 + ty + 8 * r;
        int b = row / NN, n = row % NN;
        float a0, a1;
        unpk(acc[r], a0, a1);
        int o0 = 2 * tx, o1 = 2 * tx + 1;
        float u0 = xs[ty + 8 * r][o0] + a0 + B2f[o0];
        float u1 = xs[ty + 8 * r][o1] + a1 + B2f[o1];
        float s = u0 + u1, q = u0 * u0 + u1 * u1;
        for (int off = 16; off; off >>= 1) {
            s += __shfl_xor_sync(~0u, s, off);
            q += __shfl_xor_sync(~0u, q, off);
        }
        float mean = s / 64.f, var = q / 64.f - mean * mean;
        float rs = rsqrtf(var + 1e-5f);
        float o20 = (u0 - mean) * rs * g2[o0] + b2l[o0];
        float o21 = (u1 - mean) * rs * g2[o1] + b2l[o1];
        size_t hb = (size_t)row * 64;
        float c0 = HL[hb + o0] * wsp[(size_t)n * 64 + o0] + o20 * wtp[(size_t)n * 64 + o0];
        float c1 = HL[hb + o1] * wsp[(size_t)n * 64 + o1] + o21 * wtp[(size_t)n * 64 + o1];
        for (int to = 0; to < 12; to++) {
            float p = c0 * cw[to * 64 + o0] + c1 * cw[to * 64 + o1];
            for (int off = 16; off; off >>= 1) p += __shfl_xor_sync(~0u, p, off);
            if (tx == 0) OUT[((size_t)b * 12 + to) * NN + n] = p + cb[to];
        }
    }
}

// ---------------- launch ----------------
extern "C" void kernel_launch(void* const* d_in, const int* in_sizes, int n_in,
                              void* d_out, int out_size) {
    const float* src  = (const float*)d_in[0];
    const float* ne   = (const float*)d_in[1];
    const float* gw0  = (const float*)d_in[2];
    const float* gb0  = (const float*)d_in[3];
    const float* uw0  = (const float*)d_in[4];
    const float* ub0  = (const float*)d_in[5];
    const float* gw1  = (const float*)d_in[6];
    const float* gb1  = (const float*)d_in[7];
    const float* uw1  = (const float*)d_in[8];
    const float* ub1  = (const float*)d_in[9];
    const float* mlpw = (const float*)d_in[10];
    const float* mlpb = (const float*)d_in[11];
    const float* wq = (const float*)d_in[12]; const float* bq = (const float*)d_in[13];
    const float* wk = (const float*)d_in[14]; const float* bk = (const float*)d_in[15];
    const float* wv = (const float*)d_in[16]; const float* bv = (const float*)d_in[17];
    const float* wo = (const float*)d_in[18]; const float* bo = (const float*)d_in[19];
    const float* fw1 = (const float*)d_in[20]; const float* fb1 = (const float*)d_in[21];
    const float* fw2 = (const float*)d_in[22]; const float* fb2 = (const float*)d_in[23];
    const float* l1g = (const float*)d_in[24]; const float* l1b = (const float*)d_in[25];
    const float* l2g = (const float*)d_in[26]; const float* l2b = (const float*)d_in[27];
    const float* wsp = (const float*)d_in[28]; const float* wtp = (const float*)d_in[29];
    const float* cw  = (const float*)d_in[30]; const float* cb  = (const float*)d_in[31];
    float* out = (float*)d_out;

    float* G;
    cudaGetSymbolAddress((void**)&G, g_mem);
    unsigned int* barAddr;
    cudaGetSymbolAddress((void**)&barAddr, g_bar);
    int smCount = 148;
    cudaDeviceGetAttribute(&smCount, cudaDevAttrMultiProcessorCount, 0);
    int pgrid = smCount * 2;

    float* A    = G + O_A;    float* ATr  = G + O_ATR;
    float* WHG0 = G + O_WHG0; float* WHU0 = G + O_WHU0;
    float* WXG0 = G + O_WXG0; float* WXU0 = G + O_WXU0;
    float* WHG1 = G + O_WHG1; float* WHU1 = G + O_WHU1;
    float* WXG1 = G + O_WXG1; float* WXU1 = G + O_WXU1;
    float* BG0  = G + O_BG0;  float* BU0  = G + O_BU0;
    float* BG1  = G + O_BG1;  float* BU1  = G + O_BU1;
    float* AX0  = G + O_AX0;
    float* XCG0 = G + O_XCG0; float* XCU0 = G + O_XCU0;
    float* XCG1 = G + O_XCG1; float* XCU1 = G + O_XCU1;
    float* HS0  = G + O_HS0;  float* AX1  = G + O_AX1;
    float* H    = G + O_H;    float* AH   = G + O_AH;
    float* ZH   = G + O_ZH;   float* AZH  = G + O_AZH;
    float* R    = G + O_R;    float* O1   = G + O_O1;
    float* TBL  = G + O_TBL;

    adj_kernel<<<NN, 128>>>(ne, A, ATr);

    auto blocks = [](int total) { return (total + 255) / 256; };
    int tWH = NN * 128 * 128, tWU = NN * 128 * 64;
    wmix_kernel<<<blocks(tWH), 256>>>(ne, gw0, WHG0, 128, 128, 65, 1, 64, tWH);
    wmix_kernel<<<blocks(tWU), 256>>>(ne, uw0, WHU0, 128, 64, 65, 1, 64, tWU);
    wmix_kernel<<<blocks(NN * 2 * 128), 256>>>(ne, gw0, WXG0, 2, 128, 65, 0, 1, NN * 2 * 128);
    wmix_kernel<<<blocks(NN * 2 * 64), 256>>>(ne, uw0, WXU0, 2, 64, 65, 0, 1, NN * 2 * 64);
    wmix_kernel<<<blocks(tWH), 256>>>(ne, gw1, WHG1, 128, 128, 128, 64, 64, tWH);
    wmix_kernel<<<blocks(tWU), 256>>>(ne, uw1, WHU1, 128, 64, 128, 64, 64, tWU);
    wmix_kernel<<<blocks(tWH), 256>>>(ne, gw1, WXG1, 128, 128, 128, 0, 64, tWH);
    wmix_kernel<<<blocks(tWU), 256>>>(ne, uw1, WXU1, 128, 64, 128, 0, 64, tWU);
    bmix_kernel<<<blocks(NN * 128), 256>>>(ne, gb0, BG0, 128, NN * 128);
    bmix_kernel<<<blocks(NN * 64), 256>>>(ne, ub0, BU0, 64, NN * 64);
    bmix_kernel<<<blocks(NN * 128), 256>>>(ne, gb1, BG1, 128, NN * 128);
    bmix_kernel<<<blocks(NN * 64), 256>>>(ne, ub1, BU1, 64, NN * 64);

    ax0_kernel<<<MT, 320>>>(ATr, src, AX0);
    xc0_kernel<128><<<blocks(MT * NN * 128), 256>>>(src, AX0, WXG0, BG0, XCG0);
    xc0_kernel<64><<<blocks(MT * NN * 64), 256>>>(src, AX0, WXU0, BU0, XCU0);

    int hbN = BB * NN * 64;
    // ---- layer 0 (persistent) ----
    step0_kernel<<<blocks(hbN), 256>>>(XCG0, XCU0, H, HS0);
    cudaMemsetAsync(barAddr, 0, sizeof(unsigned int));
    gru_loop<<<pgrid, 256>>>(A, WHG0, WHU0, XCG0, XCU0, H, AH, ZH, AZH, R, HS0);

    // ---- layer-1 x-contributions (parallel over all t) ----
    av_kernel<<<dim3(10, MT), 256>>>(A, HS0, AX1);
    node_gemm<128, 0><<<dim3(NN, 12), 256>>>(HS0, AX1, WXG1, BG1, nullptr, nullptr, XCG1, nullptr);
    node_gemm<64, 0><<<dim3(NN, 12), 256>>>(HS0, AX1, WXU1, BU1, nullptr, nullptr, XCU1, nullptr);

    // ---- layer 1 (persistent) ----
    step0_kernel<<<blocks(hbN), 256>>>(XCG1, XCU1, H, H);
    cudaMemsetAsync(barAddr, 0, sizeof(unsigned int));
    gru_loop<<<pgrid, 256>>>(A, WHG1, WHU1, XCG1, XCU1, H, AH, ZH, AZH, R, nullptr);

    attn_prep<<<1, 64>>>(mlpw, mlpb, wq, bq, wk, bk, wv, bv, TBL);
    attn_main<<<(BN + 63) / 64, 256>>>(src, mlpw, wo, bo, l1g, l1b, TBL, O1);
    ffn_kernel<<<NN, 256>>>(O1, fw1, fb1, fw2, fb2, l2g, l2b, H, wsp, wtp, cw, cb, out);
}

// round 11
// speedup vs baseline: 1.0160x; 1.0160x over previous
#include <cuda_runtime.h>
#include <math.h>

constexpr int NN = 307, TT = 12, BB = 32, EE = 10;
constexpr int MT = TT * BB;   // 384
constexpr int BN = BB * NN;   // 9824

// ---------------- f32x2 helpers ----------------
typedef unsigned long long ull;
__device__ __forceinline__ ull pk2(float x) {
    ull r; asm("mov.b64 %0, {%1, %1};" : "=l"(r) : "f"(x)); return r;
}
__device__ __forceinline__ ull pk(float a, float b) {
    ull r; asm("mov.b64 %0, {%1, %2};" : "=l"(r) : "f"(a), "f"(b)); return r;
}
__device__ __forceinline__ void ffma2(ull& d, ull a, ull b) {
    asm("fma.rn.f32x2 %0, %1, %2, %0;" : "+l"(d) : "l"(a), "l"(b));
}
__device__ __forceinline__ void unpk(ull v, float& a, float& b) {
    asm("mov.b64 {%0, %1}, %2;" : "=f"(a), "=f"(b) : "l"(v));
}
// fast transcendentals (MUFU-based, rel err ~1e-6)
__device__ __forceinline__ float fsig(float x) {
    return __fdividef(1.f, 1.f + __expf(-x));
}
__device__ __forceinline__ float ftanh(float x) {
    return __fdividef(2.f, 1.f + __expf(-2.f * x)) - 1.f;
}

// ---------------- scratch arena (ALL offsets 16B-aligned) ----------------
constexpr size_t AL(size_t x) { return (x + 3) & ~(size_t)3; }

constexpr size_t S_A  = (size_t)NN * NN;
constexpr size_t S_WH = (size_t)NN * 128 * 128;
constexpr size_t S_WU = (size_t)NN * 128 * 64;
constexpr size_t S_BG = (size_t)NN * 128;
constexpr size_t S_BU = (size_t)NN * 64;
constexpr size_t S_XG = (size_t)MT * NN * 128;
constexpr size_t S_XU = (size_t)MT * NN * 64;
constexpr size_t S_HS = (size_t)MT * NN * 64;
constexpr size_t S_HB = (size_t)BB * NN * 64;

constexpr size_t O_A    = 0;
constexpr size_t O_ATR  = AL(O_A    + S_A);
constexpr size_t O_WHG0 = AL(O_ATR  + S_A);
constexpr size_t O_WHU0 = AL(O_WHG0 + S_WH);
constexpr size_t O_WXG0 = AL(O_WHU0 + S_WU);
constexpr size_t O_WXU0 = AL(O_WXG0 + (size_t)NN * 2 * 128);
constexpr size_t O_WHG1 = AL(O_WXU0 + (size_t)NN * 2 * 64);
constexpr size_t O_WHU1 = AL(O_WHG1 + S_WH);
constexpr size_t O_WXG1 = AL(O_WHU1 + S_WU);
constexpr size_t O_WXU1 = AL(O_WXG1 + S_WH);
constexpr size_t O_BG0  = AL(O_WXU1 + S_WU);
constexpr size_t O_BU0  = AL(O_BG0  + S_BG);
constexpr size_t O_BG1  = AL(O_BU0  + S_BU);
constexpr size_t O_BU1  = AL(O_BG1  + S_BG);
constexpr size_t O_AX0  = AL(O_BU1  + S_BU);
constexpr size_t O_XCG0 = AL(O_AX0  + (size_t)MT * NN);
constexpr size_t O_XCU0 = AL(O_XCG0 + S_XG);
constexpr size_t O_XCG1 = AL(O_XCU0 + S_XU);
constexpr size_t O_XCU1 = AL(O_XCG1 + S_XG);
constexpr size_t O_HS0  = AL(O_XCU1 + S_XU);
constexpr size_t O_AX1  = AL(O_HS0  + S_HS);
constexpr size_t O_H    = AL(O_AX1  + S_HS);
constexpr size_t O_AH   = AL(O_H    + S_HB);
constexpr size_t O_ZH   = AL(O_AH   + S_HB);
constexpr size_t O_AZH  = AL(O_ZH   + S_HB);
constexpr size_t O_R    = AL(O_AZH  + S_HB);
constexpr size_t O_O1   = AL(O_R    + S_HB);
constexpr size_t O_TBL  = AL(O_O1   + S_HB);
constexpr size_t TOTAL  = O_TBL  + 2048;

__device__ __align__(16) float g_mem[TOTAL];

// ---------------- adjacency ----------------
__global__ void adj_kernel(const float* __restrict__ ne, float* __restrict__ A,
                           float* __restrict__ AT) {
    int n = blockIdx.x, tid = threadIdx.x;
    __shared__ float nen[EE];
    __shared__ float rowv[NN];
    __shared__ float red[4];
    if (tid < EE) nen[tid] = ne[n * EE + tid];
    __syncthreads();
    float lmax = -1e30f;
    for (int m = tid; m < NN; m += 128) {
        float d = 0.f;
#pragma unroll
        for (int e = 0; e < EE; e++) d += nen[e] * ne[m * EE + e];
        d = fmaxf(d, 0.f);
        rowv[m] = d;
        lmax = fmaxf(lmax, d);
    }
    for (int o = 16; o; o >>= 1) lmax = fmaxf(lmax, __shfl_xor_sync(~0u, lmax, o));
    if ((tid & 31) == 0) red[tid >> 5] = lmax;
    __syncthreads();
    float bmax = fmaxf(fmaxf(red[0], red[1]), fmaxf(red[2], red[3]));
    float lsum = 0.f;
    for (int m = tid; m < NN; m += 128) {
        float e = __expf(rowv[m] - bmax);
        rowv[m] = e;
        lsum += e;
    }
    for (int o = 16; o; o >>= 1) lsum += __shfl_xor_sync(~0u, lsum, o);
    __syncthreads();
    if ((tid & 31) == 0) red[tid >> 5] = lsum;
    __syncthreads();
    float inv = 1.f / (red[0] + red[1] + red[2] + red[3]);
    for (int m = tid; m < NN; m += 128) {
        float v = rowv[m] * inv;
        A[(size_t)n * NN + m]  = v;
        AT[(size_t)m * NN + n] = v;
    }
}

// ---------------- per-node weight/bias mixing ----------------
__global__ void wmix_kernel(const float* __restrict__ ne, const float* __restrict__ src,
                            float* __restrict__ dst, int R, int O, int Isrc, int ioff,
                            int rdiv, int total) {
    int idx = blockIdx.x * blockDim.x + threadIdx.x;
    if (idx >= total) return;
    int o = idx % O;
    int r = (idx / O) % R;
    int n = idx / (O * R);
    int k = r / rdiv;
    int i = ioff + (r % rdiv);
    float acc = 0.f;
#pragma unroll
    for (int e = 0; e < EE; e++)
        acc += ne[n * EE + e] * src[(((size_t)e * 2 + k) * Isrc + i) * O + o];
    dst[idx] = acc;
}

__global__ void bmix_kernel(const float* __restrict__ ne, const float* __restrict__ src,
                            float* __restrict__ dst, int O, int total) {
    int idx = blockIdx.x * blockDim.x + threadIdx.x;
    if (idx >= total) return;
    int o = idx % O, n = idx / O;
    float acc = 0.f;
#pragma unroll
    for (int e = 0; e < EE; e++) acc += ne[n * EE + e] * src[e * O + o];
    dst[idx] = acc;
}

// ---------------- ax0[m][n] = sum_mm A[n][mm]*src[b,t,mm], m=t*32+b ----------------
__global__ void ax0_kernel(const float* __restrict__ AT, const float* __restrict__ src,
                           float* __restrict__ ax0) {
    int m = blockIdx.x;
    int b = m & 31, t = m >> 5;
    __shared__ float ss[NN];
    int tid = threadIdx.x;  // 320
    if (tid < NN) ss[tid] = src[((size_t)b * TT + t) * NN + tid];
    __syncthreads();
    if (tid < NN) {
        float acc = 0.f;
        for (int mm = 0; mm < NN; mm++) acc += AT[(size_t)mm * NN + tid] * ss[mm];
        ax0[(size_t)m * NN + tid] = acc;
    }
}

// ---------------- layer-0 x-contribution ----------------
template <int O>
__global__ void xc0_kernel(const float* __restrict__ src, const float* __restrict__ ax0,
                           const float* __restrict__ Wx, const float* __restrict__ Bv,
                           float* __restrict__ xc) {
    size_t idx = (size_t)blockIdx.x * blockDim.x + threadIdx.x;
    if (idx >= (size_t)MT * NN * O) return;
    int o = (int)(idx % O);
    int n = (int)((idx / O) % NN);
    int m = (int)(idx / ((size_t)O * NN));
    int b = m & 31, t = m >> 5;
    float s = src[((size_t)b * TT + t) * NN + n];
    float a = ax0[(size_t)m * NN + n];
    xc[idx] = s * Wx[((size_t)n * 2) * O + o] + a * Wx[((size_t)n * 2 + 1) * O + o]
            + Bv[(size_t)n * O + o];
}

// ---------------- t=0 specialized step ----------------
__global__ void step0_kernel(const float* __restrict__ XCG, const float* __restrict__ XCU,
                             float* __restrict__ H, float* __restrict__ HS) {
    int idx = blockIdx.x * blockDim.x + threadIdx.x;
    if (idx >= BB * NN * 64) return;
    int ib = idx >> 6, o = idx & 63;
    float r = fsig(XCG[(size_t)ib * 128 + 64 + o]);
    float hc = ftanh(XCU[idx]);
    float h = (1.f - r) * hc;
    H[idx] = h;
    HS[idx] = h;
}

// ---------------- batched A @ V (coalesced via AT), 3 blocks/SM ----------------
// OUT[bb][n][c] = sum_m A[n][m] V[bb][m][c] ;  A[n][m] = AT[m*NN+n]
__global__ void __launch_bounds__(256, 3) av_kernel(
        const float* __restrict__ AT, const float* __restrict__ V,
        float* __restrict__ OUT) {
    __shared__ __align__(16) float vs[32 * 64];
    __shared__ __align__(16) float as_[32 * 34];
    int n0 = blockIdx.x * 32, bb = blockIdx.y;
    const float* Vb = V + (size_t)bb * NN * 64;
    float* Ob = OUT + (size_t)bb * NN * 64;
    int tid = threadIdx.x, tx = tid & 31, ty = tid >> 5;
    ull acc[2][2] = {{0ull, 0ull}, {0ull, 0ull}};
#pragma unroll 1
    for (int m0 = 0; m0 < NN; m0 += 32) {
        __syncthreads();
#pragma unroll
        for (int s = 0; s < 2; s++) {
            int q = tid + s * 256;
            int mm = q >> 4, c4 = (q & 15) * 4;
            int m = m0 + mm;
            float4 v = (m < NN) ? *reinterpret_cast<const float4*>(&Vb[(size_t)m * 64 + c4])
                                : make_float4(0.f, 0.f, 0.f, 0.f);
            *reinterpret_cast<float4*>(&vs[mm * 64 + c4]) = v;
        }
#pragma unroll
        for (int s = 0; s < 4; s++) {
            int i = tid + s * 256;
            int mm = i >> 5, j = i & 31;            // coalesced: consecutive j
            int m = m0 + mm, n2 = n0 + j;
            as_[mm * 34 + j] = (m < NN && n2 < NN) ? AT[(size_t)m * NN + n2] : 0.f;
        }
        __syncthreads();
#pragma unroll
        for (int mm = 0; mm < 32; mm++) {
            ull a01 = *reinterpret_cast<const ull*>(&as_[mm * 34 + 4 * ty]);
            ull a23 = *reinterpret_cast<const ull*>(&as_[mm * 34 + 4 * ty + 2]);
            ull v0 = pk2(vs[mm * 64 + tx]);
            ull v1 = pk2(vs[mm * 64 + tx + 32]);
            ffma2(acc[0][0], a01, v0);
            ffma2(acc[1][0], a23, v0);
            ffma2(acc[0][1], a01, v1);
            ffma2(acc[1][1], a23, v1);
        }
    }
    int nb = n0 + 4 * ty;
    float o00, o01, o10, o11, o20, o21, o30, o31;
    unpk(acc[0][0], o00, o10);
    unpk(acc[1][0], o20, o30);
    unpk(acc[0][1], o01, o11);
    unpk(acc[1][1], o21, o31);
    if (nb < NN)     { Ob[(size_t)nb * 64 + tx] = o00;       Ob[(size_t)nb * 64 + tx + 32] = o01; }
    if (nb + 1 < NN) { Ob[(size_t)(nb+1) * 64 + tx] = o10;   Ob[(size_t)(nb+1) * 64 + tx + 32] = o11; }
    if (nb + 2 < NN) { Ob[(size_t)(nb+2) * 64 + tx] = o20;   Ob[(size_t)(nb+2) * 64 + tx + 32] = o21; }
    if (nb + 3 < NN) { Ob[(size_t)(nb+3) * 64 + tx] = o30;   Ob[(size_t)(nb+3) * 64 + tx + 32] = o31; }
}

// ---------------- per-node GEMM, f32x2 col-pairs, 3 blocks/SM ----------------
// MODE 0: C = acc + AX[n][o]
// MODE 1: v=sigmoid(acc+AX[ib]); o<64 -> C2=v*HOLD ; o>=64 -> C=v
// MODE 2: hc=tanh(acc+AX[ib]); hn=RB*HOLD+(1-RB)*hc -> C and C2
template <int O, int MODE>
__global__ void __launch_bounds__(256, 3) node_gemm(
        const float* __restrict__ X1, const float* __restrict__ X2,
        const float* __restrict__ W, const float* __restrict__ AX,
        const float* __restrict__ RB, const float* __restrict__ HOLD,
        float* __restrict__ C, float* __restrict__ C2) {
    constexpr int NP = O / 64;
    constexpr int WV = O / 32;
    __shared__ __align__(16) float xs[32 * 128];
    __shared__ __align__(16) float ws[32 * O];
    int n = blockIdx.x, m0 = blockIdx.y * 32;
    int tid = threadIdx.x, tx = tid & 31, ty = tid >> 5;
#pragma unroll
    for (int s = 0; s < 4; s++) {
        int q = tid + s * 256;
        int m = q >> 5, j4 = (q & 31) * 4;
        const float* sp = (j4 < 64) ? X1 : X2;
        float4 v = *reinterpret_cast<const float4*>(
            &sp[((size_t)(m0 + m) * NN + n) * 64 + (j4 & 63)]);
        *reinterpret_cast<float4*>(&xs[m * 128 + j4]) = v;
    }
    const float* Wn = W + (size_t)n * 128 * O;
    ull acc[4][NP];
#pragma unroll
    for (int r = 0; r < 4; r++)
#pragma unroll
        for (int p = 0; p < NP; p++) acc[r][p] = 0ull;
#pragma unroll 1
    for (int k0 = 0; k0 < 4; k0++) {
        __syncthreads();
        const float4* Wt = reinterpret_cast<const float4*>(Wn + (size_t)k0 * 32 * O);
#pragma unroll
        for (int s = 0; s < WV; s++)
            reinterpret_cast<float4*>(ws)[tid + s * 256] = Wt[tid + s * 256];
        __syncthreads();
#pragma unroll
        for (int kk = 0; kk < 32; kk++) {
            ull wp[NP];
#pragma unroll
            for (int p = 0; p < NP; p++)
                wp[p] = *reinterpret_cast<const ull*>(&ws[kk * O + 2 * tx + 64 * p]);
#pragma unroll
            for (int r = 0; r < 4; r++) {
                ull xp = pk2(xs[(ty + 8 * r) * 128 + k0 * 32 + kk]);
#pragma unroll
                for (int p = 0; p < NP; p++) ffma2(acc[r][p], xp, wp[p]);
            }
        }
    }
#pragma unroll
    for (int r = 0; r < 4; r++) {
        int m = m0 + ty + 8 * r;
        size_t ib = (size_t)m * NN + n;
#pragma unroll
        for (int p = 0; p < NP; p++) {
            float v0, v1;
            unpk(acc[r][p], v0, v1);
            int o0 = 2 * tx + 64 * p;
            if (MODE == 0) {
                C[ib * O + o0]     = v0 + AX[(size_t)n * O + o0];
                C[ib * O + o0 + 1] = v1 + AX[(size_t)n * O + o0 + 1];
            } else if (MODE == 1) {
                float s0 = fsig(v0 + AX[ib * O + o0]);
                float s1 = fsig(v1 + AX[ib * O + o0 + 1]);
                if (p == 0) {
                    C2[ib * 64 + o0]     = s0 * HOLD[ib * 64 + o0];
                    C2[ib * 64 + o0 + 1] = s1 * HOLD[ib * 64 + o0 + 1];
                } else {
                    C[ib * 64 + o0 - 64] = s0;
                    C[ib * 64 + o0 - 63] = s1;
                }
            } else {
                float hc0 = ftanh(v0 + AX[ib * O + o0]);
                float hc1 = ftanh(v1 + AX[ib * O + o0 + 1]);
                float r0 = RB[ib * 64 + o0], r1 = RB[ib * 64 + o0 + 1];
                float hd0 = HOLD[ib * 64 + o0], hd1 = HOLD[ib * 64 + o0 + 1];
                float h0 = r0 * hd0 + (1.f - r0) * hc0;
                float h1 = r1 * hd1 + (1.f - r1) * hc1;
                C[ib * 64 + o0] = h0;  C[ib * 64 + o0 + 1] = h1;
                if (C2) { C2[ib * 64 + o0] = h0; C2[ib * 64 + o0 + 1] = h1; }
            }
        }
    }
}

// ---------------- attention tables ----------------
__global__ void attn_prep(const float* __restrict__ mw, const float* __restrict__ mb,
                          const float* __restrict__ wq, const float* __restrict__ bq,
                          const float* __restrict__ wk, const float* __restrict__ bk,
                          const float* __restrict__ wv, const float* __restrict__ bv,
                          float* __restrict__ tbl) {
    __shared__ float MQ[64], MK[64], CQ11[64], CK[12][64], CT[12][64];
    int o = threadIdx.x;  // 64 threads
    for (int t = 0; t < 12; t++) {
        int p = o >> 1;
        float ang = (float)t * powf(10000.f, -(float)(2 * p) / 64.f);
        CT[t][o] = mb[o] + ((o & 1) ? cosf(ang) : sinf(ang));
    }
    __syncthreads();
    float mq = 0.f, mk = 0.f, mv = 0.f;
    for (int i = 0; i < 64; i++) {
        float w = mw[i];
        mq += w * wq[i * 64 + o];
        mk += w * wk[i * 64 + o];
        mv += w * wv[i * 64 + o];
    }
    MQ[o] = mq; MK[o] = mk;
    tbl[o] = mv;
    tbl[64 + o] = CT[11][o];
    float cq = bq[o];
    for (int i = 0; i < 64; i++) cq += CT[11][i] * wq[i * 64 + o];
    CQ11[o] = cq;
    for (int t = 0; t < 12; t++) {
        float ck = bk[o], cv = bv[o];
        for (int i = 0; i < 64; i++) {
            float c = CT[t][i];
            ck += c * wk[i * 64 + o];
            cv += c * wv[i * 64 + o];
        }
        CK[t][o] = ck;
        tbl[128 + t * 64 + o] = cv;
    }
    __syncthreads();
    if (o < 4) {
        float a = 0.f, c = 0.f;
        for (int d = 0; d < 16; d++) {
            a += MQ[o * 16 + d] * MK[o * 16 + d];
            c += CQ11[o * 16 + d] * MK[o * 16 + d];
        }
        tbl[896 + o] = a;
        tbl[900 + o] = c;
    }
    if (o < 48) {
        int h = o / 12, s = o % 12;
        float b = 0.f, dd = 0.f;
        for (int d = 0; d < 16; d++) {
            b  += MQ[h * 16 + d] * CK[s][h * 16 + d];
            dd += CQ11[h * 16 + d] * CK[s][h * 16 + d];
        }
        tbl[904 + o] = b;
        tbl[952 + o] = dd;
    }
}

// ---------------- attention + wo + LN1 ----------------
__global__ void attn_main(const float* __restrict__ src, const float* __restrict__ mw,
                          const float* __restrict__ wo, const float* __restrict__ bo,
                          const float* __restrict__ g1, const float* __restrict__ b1,
                          const float* __restrict__ tblg, float* __restrict__ O1) {
    __shared__ float tbl[1000];
    __shared__ float wos[4096];
    __shared__ float ovs[64][65];
    int tid = threadIdx.x;
    for (int i = tid; i < 1000; i += 256) tbl[i] = tblg[i];
    for (int i = tid; i < 4096; i += 256) wos[i] = wo[i];
    __syncthreads();
    int g = tid >> 2, hq = tid & 3;
    int bn = blockIdx.x * 64 + g;
    bool act = bn < BN;
    int b = act ? bn / NN : 0;
    int n = act ? bn % NN : 0;
    float sv[12];
    for (int s = 0; s < 12; s++) sv[s] = src[((size_t)b * TT + s) * NN + n];
    float sT = sv[11];
    const float* Ah = tbl + 896;
    const float* Ch = tbl + 900;
    const float* Bh = tbl + 904;
    const float* Dh = tbl + 952;
    float sc[12], smax = -1e30f;
    for (int s = 0; s < 12; s++) {
        float v = 0.25f * (sT * sv[s] * Ah[hq] + sT * Bh[hq * 12 + s]
                           + sv[s] * Ch[hq] + Dh[hq * 12 + s]);
        sc[s] = v;
        smax = fmaxf(smax, v);
    }
    float ssum = 0.f;
    for (int s = 0; s < 12; s++) { sc[s] = __expf(sc[s] - smax); ssum += sc[s]; }
    float inv = __fdividef(1.f, ssum), sa = 0.f;
    for (int s = 0; s < 12; s++) { sc[s] *= inv; sa += sc[s] * sv[s]; }
    for (int d = 0; d < 16; d++) {
        int dg = hq * 16 + d;
        float ov = sa * tbl[dg];
        for (int s = 0; s < 12; s++) ov += sc[s] * tbl[128 + s * 64 + dg];
        ovs[g][dg] = ov;
    }
    __syncthreads();
    float u[16], lsum = 0.f, lsq = 0.f;
    for (int d = 0; d < 16; d++) {
        int o = hq * 16 + d;
        float acc = bo[o];
        for (int i = 0; i < 64; i++) acc += ovs[g][i] * wos[i * 64 + o];
        float uu = sT * mw[o] + tbl[64 + o] + acc;
        u[d] = uu;
        lsum += uu;
        lsq += uu * uu;
    }
    lsum += __shfl_xor_sync(~0u, lsum, 1); lsum += __shfl_xor_sync(~0u, lsum, 2);
    lsq  += __shfl_xor_sync(~0u, lsq, 1);  lsq  += __shfl_xor_sync(~0u, lsq, 2);
    float mean = lsum / 64.f, var = lsq / 64.f - mean * mean;
    float rs = rsqrtf(var + 1e-5f);
    if (act)
        for (int d = 0; d < 16; d++) {
            int o = hq * 16 + d;
            O1[(size_t)bn * 64 + o] = (u[d] - mean) * rs * g1[o] + b1[o];
        }
}

// ---------------- FFN + LN2 + combine + conv ----------------
__global__ void __launch_bounds__(256, 3) ffn_kernel(
        const float* __restrict__ O1, const float* __restrict__ W1,
        const float* __restrict__ B1f, const float* __restrict__ W2,
        const float* __restrict__ B2f, const float* __restrict__ g2,
        const float* __restrict__ b2l, const float* __restrict__ HL,
        const float* __restrict__ wsp, const float* __restrict__ wtp,
        const float* __restrict__ cw, const float* __restrict__ cb,
        float* __restrict__ OUT) {
    __shared__ float xs[32][64];
    __shared__ float w1t[64][32];
    __shared__ float ht[32][33];
    __shared__ float w2t[32][64];
    int tid = threadIdx.x, tx = tid & 31, ty = tid >> 5;
    int m0 = blockIdx.x * 32;
    for (int i = tid; i < 2048; i += 256) {
        int a = i >> 6, c = i & 63;
        xs[a][c] = O1[(size_t)(m0 + a) * 64 + c];
    }
    ull acc[4] = {0ull, 0ull, 0ull, 0ull};
#pragma unroll 1
    for (int j0 = 0; j0 < 1024; j0 += 32) {
        __syncthreads();
        for (int i = tid; i < 2048; i += 256)
            w1t[i >> 5][i & 31] = W1[(size_t)(i >> 5) * 1024 + j0 + (i & 31)];
        for (int i = tid; i < 2048; i += 256)
            w2t[i >> 6][i & 63] = W2[(size_t)(j0 + (i >> 6)) * 64 + (i & 63)];
        __syncthreads();
#pragma unroll
        for (int rep = 0; rep < 2; rep++) {
            int slot = tid + rep * 256;
            int a = slot >> 4, bp = (slot & 15) * 2;
            ull h = pk(B1f[j0 + bp], B1f[j0 + bp + 1]);
#pragma unroll
            for (int k = 0; k < 64; k++)
                ffma2(h, pk2(xs[a][k]),
                      *reinterpret_cast<const ull*>(&w1t[k][bp]));
            float h0, h1;
            unpk(h, h0, h1);
            ht[a][bp]     = fmaxf(h0, 0.f);
            ht[a][bp + 1] = fmaxf(h1, 0.f);
        }
        __syncthreads();
#pragma unroll
        for (int jj = 0; jj < 32; jj++) {
            ull w = *reinterpret_cast<const ull*>(&w2t[jj][2 * tx]);
#pragma unroll
            for (int r = 0; r < 4; r++)
                ffma2(acc[r], pk2(ht[ty + 8 * r][jj]), w);
        }
    }
#pragma unroll
    for (int r = 0; r < 4; r++) {
        int row = m0 + ty + 8 * r;
        int b = row / NN, n = row % NN;
        float a0, a1;
        unpk(acc[r], a0, a1);
        int o0 = 2 * tx, o1 = 2 * tx + 1;
        float u0 = xs[ty + 8 * r][o0] + a0 + B2f[o0];
        float u1 = xs[ty + 8 * r][o1] + a1 + B2f[o1];
        float s = u0 + u1, q = u0 * u0 + u1 * u1;
        for (int off = 16; off; off >>= 1) {
            s += __shfl_xor_sync(~0u, s, off);
            q += __shfl_xor_sync(~0u, q, off);
        }
        float mean = s / 64.f, var = q / 64.f - mean * mean;
        float rs = rsqrtf(var + 1e-5f);
        float o20 = (u0 - mean) * rs * g2[o0] + b2l[o0];
        float o21 = (u1 - mean) * rs * g2[o1] + b2l[o1];
        size_t hb = (size_t)row * 64;
        float c0 = HL[hb + o0] * wsp[(size_t)n * 64 + o0] + o20 * wtp[(size_t)n * 64 + o0];
        float c1 = HL[hb + o1] * wsp[(size_t)n * 64 + o1] + o21 * wtp[(size_t)n * 64 + o1];
        for (int to = 0; to < 12; to++) {
            float p = c0 * cw[to * 64 + o0] + c1 * cw[to * 64 + o1];
            for (int off = 16; off; off >>= 1) p += __shfl_xor_sync(~0u, p, off);
            if (tx == 0) OUT[((size_t)b * 12 + to) * NN + n] = p + cb[to];
        }
    }
}

// ---------------- launch ----------------
extern "C" void kernel_launch(void* const* d_in, const int* in_sizes, int n_in,
                              void* d_out, int out_size) {
    const float* src  = (const float*)d_in[0];
    const float* ne   = (const float*)d_in[1];
    const float* gw0  = (const float*)d_in[2];
    const float* gb0  = (const float*)d_in[3];
    const float* uw0  = (const float*)d_in[4];
    const float* ub0  = (const float*)d_in[5];
    const float* gw1  = (const float*)d_in[6];
    const float* gb1  = (const float*)d_in[7];
    const float* uw1  = (const float*)d_in[8];
    const float* ub1  = (const float*)d_in[9];
    const float* mlpw = (const float*)d_in[10];
    const float* mlpb = (const float*)d_in[11];
    const float* wq = (const float*)d_in[12]; const float* bq = (const float*)d_in[13];
    const float* wk = (const float*)d_in[14]; const float* bk = (const float*)d_in[15];
    const float* wv = (const float*)d_in[16]; const float* bv = (const float*)d_in[17];
    const float* wo = (const float*)d_in[18]; const float* bo = (const float*)d_in[19];
    const float* fw1 = (const float*)d_in[20]; const float* fb1 = (const float*)d_in[21];
    const float* fw2 = (const float*)d_in[22]; const float* fb2 = (const float*)d_in[23];
    const float* l1g = (const float*)d_in[24]; const float* l1b = (const float*)d_in[25];
    const float* l2g = (const float*)d_in[26]; const float* l2b = (const float*)d_in[27];
    const float* wsp = (const float*)d_in[28]; const float* wtp = (const float*)d_in[29];
    const float* cw  = (const float*)d_in[30]; const float* cb  = (const float*)d_in[31];
    float* out = (float*)d_out;

    float* G;
    cudaGetSymbolAddress((void**)&G, g_mem);
    float* A    = G + O_A;    float* ATr  = G + O_ATR;
    float* WHG0 = G + O_WHG0; float* WHU0 = G + O_WHU0;
    float* WXG0 = G + O_WXG0; float* WXU0 = G + O_WXU0;
    float* WHG1 = G + O_WHG1; float* WHU1 = G + O_WHU1;
    float* WXG1 = G + O_WXG1; float* WXU1 = G + O_WXU1;
    float* BG0  = G + O_BG0;  float* BU0  = G + O_BU0;
    float* BG1  = G + O_BG1;  float* BU1  = G + O_BU1;
    float* AX0  = G + O_AX0;
    float* XCG0 = G + O_XCG0; float* XCU0 = G + O_XCU0;
    float* XCG1 = G + O_XCG1; float* XCU1 = G + O_XCU1;
    float* HS0  = G + O_HS0;  float* AX1  = G + O_AX1;
    float* H    = G + O_H;    float* AH   = G + O_AH;
    float* ZH   = G + O_ZH;   float* AZH  = G + O_AZH;
    float* R    = G + O_R;    float* O1   = G + O_O1;
    float* TBL  = G + O_TBL;

    adj_kernel<<<NN, 128>>>(ne, A, ATr);

    auto blocks = [](int total) { return (total + 255) / 256; };
    int tWH = NN * 128 * 128, tWU = NN * 128 * 64;
    wmix_kernel<<<blocks(tWH), 256>>>(ne, gw0, WHG0, 128, 128, 65, 1, 64, tWH);
    wmix_kernel<<<blocks(tWU), 256>>>(ne, uw0, WHU0, 128, 64, 65, 1, 64, tWU);
    wmix_kernel<<<blocks(NN * 2 * 128), 256>>>(ne, gw0, WXG0, 2, 128, 65, 0, 1, NN * 2 * 128);
    wmix_kernel<<<blocks(NN * 2 * 64), 256>>>(ne, uw0, WXU0, 2, 64, 65, 0, 1, NN * 2 * 64);
    wmix_kernel<<<blocks(tWH), 256>>>(ne, gw1, WHG1, 128, 128, 128, 64, 64, tWH);
    wmix_kernel<<<blocks(tWU), 256>>>(ne, uw1, WHU1, 128, 64, 128, 64, 64, tWU);
    wmix_kernel<<<blocks(tWH), 256>>>(ne, gw1, WXG1, 128, 128, 128, 0, 64, tWH);
    wmix_kernel<<<blocks(tWU), 256>>>(ne, uw1, WXU1, 128, 64, 128, 0, 64, tWU);
    bmix_kernel<<<blocks(NN * 128), 256>>>(ne, gb0, BG0, 128, NN * 128);
    bmix_kernel<<<blocks(NN * 64), 256>>>(ne, ub0, BU0, 64, NN * 64);
    bmix_kernel<<<blocks(NN * 128), 256>>>(ne, gb1, BG1, 128, NN * 128);
    bmix_kernel<<<blocks(NN * 64), 256>>>(ne, ub1, BU1, 64, NN * 64);

    ax0_kernel<<<MT, 320>>>(ATr, src, AX0);
    xc0_kernel<128><<<blocks(MT * NN * 128), 256>>>(src, AX0, WXG0, BG0, XCG0);
    xc0_kernel<64><<<blocks(MT * NN * 64), 256>>>(src, AX0, WXU0, BU0, XCU0);

    int hbN = BB * NN * 64;
    // ---- layer 0 ----
    step0_kernel<<<blocks(hbN), 256>>>(XCG0, XCU0, H, HS0);
    for (int t = 1; t < TT; t++) {
        av_kernel<<<dim3(10, BB), 256>>>(ATr, H, AH);
        node_gemm<128, 1><<<dim3(NN, 1), 256>>>(H, AH, WHG0,
            XCG0 + (size_t)t * BB * NN * 128, nullptr, H, R, ZH);
        av_kernel<<<dim3(10, BB), 256>>>(ATr, ZH, AZH);
        node_gemm<64, 2><<<dim3(NN, 1), 256>>>(ZH, AZH, WHU0,
            XCU0 + (size_t)t * BB * NN * 64, R, H, H, HS0 + (size_t)t * BB * NN * 64);
    }

    // ---- layer-1 x-contributions (parallel over all t) ----
    av_kernel<<<dim3(10, MT), 256>>>(ATr, HS0, AX1);
    node_gemm<128, 0><<<dim3(NN, 12), 256>>>(HS0, AX1, WXG1, BG1, nullptr, nullptr, XCG1, nullptr);
    node_gemm<64, 0><<<dim3(NN, 12), 256>>>(HS0, AX1, WXU1, BU1, nullptr, nullptr, XCU1, nullptr);

    // ---- layer 1 ----
    step0_kernel<<<blocks(hbN), 256>>>(XCG1, XCU1, H, H);
    for (int t = 1; t < TT; t++) {
        av_kernel<<<dim3(10, BB), 256>>>(ATr, H, AH);
        node_gemm<128, 1><<<dim3(NN, 1), 256>>>(H, AH, WHG1,
            XCG1 + (size_t)t * BB * NN * 128, nullptr, H, R, ZH);
        av_kernel<<<dim3(10, BB), 256>>>(ATr, ZH, AZH);
        node_gemm<64, 2><<<dim3(NN, 1), 256>>>(ZH, AZH, WHU1,
            XCU1 + (size_t)t * BB * NN * 64, R, H, H, H);
    }

    attn_prep<<<1, 64>>>(mlpw, mlpb, wq, bq, wk, bk, wv, bv, TBL);
    attn_main<<<(BN + 63) / 64, 256>>>(src, mlpw, wo, bo, l1g, l1b, TBL, O1);
    ffn_kernel<<<NN, 256>>>(O1, fw1, fb1, fw2, fb2, l2g, l2b, H, wsp, wtp, cw, cb, out);
}

// round 14
// speedup vs baseline: 1.1112x; 1.0936x over previous
#include <cuda_runtime.h>
#include <math.h>

constexpr int NN = 307, TT = 12, BB = 32, EE = 10;
constexpr int MT = TT * BB;   // 384
constexpr int BN = BB * NN;   // 9824

// ---------------- f32x2 helpers ----------------
typedef unsigned long long ull;
__device__ __forceinline__ ull pk2(float x) {
    ull r; asm("mov.b64 %0, {%1, %1};" : "=l"(r) : "f"(x)); return r;
}
__device__ __forceinline__ ull pk(float a, float b) {
    ull r; asm("mov.b64 %0, {%1, %2};" : "=l"(r) : "f"(a), "f"(b)); return r;
}
__device__ __forceinline__ void ffma2(ull& d, ull a, ull b) {
    asm("fma.rn.f32x2 %0, %1, %2, %0;" : "+l"(d) : "l"(a), "l"(b));
}
__device__ __forceinline__ void unpk(ull v, float& a, float& b) {
    asm("mov.b64 {%0, %1}, %2;" : "=f"(a), "=f"(b) : "l"(v));
}
// fast transcendentals (MUFU-based, rel err ~1e-6)
__device__ __forceinline__ float fsig(float x) {
    return __fdividef(1.f, 1.f + __expf(-x));
}
__device__ __forceinline__ float ftanh(float x) {
    return __fdividef(2.f, 1.f + __expf(-2.f * x)) - 1.f;
}

// ---------------- scratch arena (ALL offsets 16B-aligned) ----------------
constexpr size_t AL(size_t x) { return (x + 3) & ~(size_t)3; }

constexpr size_t S_A  = (size_t)NN * NN;
constexpr size_t S_WH = (size_t)NN * 128 * 128;
constexpr size_t S_WU = (size_t)NN * 128 * 64;
constexpr size_t S_BG = (size_t)NN * 128;
constexpr size_t S_BU = (size_t)NN * 64;
constexpr size_t S_XG = (size_t)MT * NN * 128;
constexpr size_t S_XU = (size_t)MT * NN * 64;
constexpr size_t S_HS = (size_t)MT * NN * 64;
constexpr size_t S_HB = (size_t)BB * NN * 64;

constexpr size_t O_A    = 0;
constexpr size_t O_ATR  = AL(O_A    + S_A);
constexpr size_t O_WHG0 = AL(O_ATR  + S_A);
constexpr size_t O_WHU0 = AL(O_WHG0 + S_WH);
constexpr size_t O_WXG0 = AL(O_WHU0 + S_WU);
constexpr size_t O_WXU0 = AL(O_WXG0 + (size_t)NN * 2 * 128);
constexpr size_t O_WHG1 = AL(O_WXU0 + (size_t)NN * 2 * 64);
constexpr size_t O_WHU1 = AL(O_WHG1 + S_WH);
constexpr size_t O_WXG1 = AL(O_WHU1 + S_WU);
constexpr size_t O_WXU1 = AL(O_WXG1 + S_WH);
constexpr size_t O_BG0  = AL(O_WXU1 + S_WU);
constexpr size_t O_BU0  = AL(O_BG0  + S_BG);
constexpr size_t O_BG1  = AL(O_BU0  + S_BU);
constexpr size_t O_BU1  = AL(O_BG1  + S_BG);
constexpr size_t O_AX0  = AL(O_BU1  + S_BU);
constexpr size_t O_XCG0 = AL(O_AX0  + (size_t)MT * NN);
constexpr size_t O_XCU0 = AL(O_XCG0 + S_XG);
constexpr size_t O_XCG1 = AL(O_XCU0 + S_XU);
constexpr size_t O_XCU1 = AL(O_XCG1 + S_XG);
constexpr size_t O_HS0  = AL(O_XCU1 + S_XU);
constexpr size_t O_AX1  = AL(O_HS0  + S_HS);
constexpr size_t O_H    = AL(O_AX1  + S_HS);
constexpr size_t O_AH   = AL(O_H    + S_HB);
constexpr size_t O_ZH   = AL(O_AH   + S_HB);
constexpr size_t O_AZH  = AL(O_ZH   + S_HB);
constexpr size_t O_R    = AL(O_AZH  + S_HB);
constexpr size_t O_O1   = AL(O_R    + S_HB);
constexpr size_t O_TBL  = AL(O_O1   + S_HB);
constexpr size_t TOTAL  = O_TBL  + 2048;

__device__ __align__(16) float g_mem[TOTAL];

// ---------------- adjacency ----------------
__global__ void adj_kernel(const float* __restrict__ ne, float* __restrict__ A,
                           float* __restrict__ AT) {
    int n = blockIdx.x, tid = threadIdx.x;
    __shared__ float nen[EE];
    __shared__ float rowv[NN];
    __shared__ float red[4];
    if (tid < EE) nen[tid] = ne[n * EE + tid];
    __syncthreads();
    float lmax = -1e30f;
    for (int m = tid; m < NN; m += 128) {
        float d = 0.f;
#pragma unroll
        for (int e = 0; e < EE; e++) d += nen[e] * ne[m * EE + e];
        d = fmaxf(d, 0.f);
        rowv[m] = d;
        lmax = fmaxf(lmax, d);
    }
    for (int o = 16; o; o >>= 1) lmax = fmaxf(lmax, __shfl_xor_sync(~0u, lmax, o));
    if ((tid & 31) == 0) red[tid >> 5] = lmax;
    __syncthreads();
    float bmax = fmaxf(fmaxf(red[0], red[1]), fmaxf(red[2], red[3]));
    float lsum = 0.f;
    for (int m = tid; m < NN; m += 128) {
        float e = __expf(rowv[m] - bmax);
        rowv[m] = e;
        lsum += e;
    }
    for (int o = 16; o; o >>= 1) lsum += __shfl_xor_sync(~0u, lsum, o);
    __syncthreads();
    if ((tid & 31) == 0) red[tid >> 5] = lsum;
    __syncthreads();
    float inv = 1.f / (red[0] + red[1] + red[2] + red[3]);
    for (int m = tid; m < NN; m += 128) {
        float v = rowv[m] * inv;
        A[(size_t)n * NN + m]  = v;
        AT[(size_t)m * NN + n] = v;
    }
}

// ---------------- per-node weight/bias mixing ----------------
__global__ void wmix_kernel(const float* __restrict__ ne, const float* __restrict__ src,
                            float* __restrict__ dst, int R, int O, int Isrc, int ioff,
                            int rdiv, int total) {
    int idx = blockIdx.x * blockDim.x + threadIdx.x;
    if (idx >= total) return;
    int o = idx % O;
    int r = (idx / O) % R;
    int n = idx / (O * R);
    int k = r / rdiv;
    int i = ioff + (r % rdiv);
    float acc = 0.f;
#pragma unroll
    for (int e = 0; e < EE; e++)
        acc += ne[n * EE + e] * src[(((size_t)e * 2 + k) * Isrc + i) * O + o];
    dst[idx] = acc;
}

__global__ void bmix_kernel(const float* __restrict__ ne, const float* __restrict__ src,
                            float* __restrict__ dst, int O, int total) {
    int idx = blockIdx.x * blockDim.x + threadIdx.x;
    if (idx >= total) return;
    int o = idx % O, n = idx / O;
    float acc = 0.f;
#pragma unroll
    for (int e = 0; e < EE; e++) acc += ne[n * EE + e] * src[e * O + o];
    dst[idx] = acc;
}

// ---------------- ax0[m][n] = sum_mm A[n][mm]*src[b,t,mm], m=t*32+b ----------------
__global__ void ax0_kernel(const float* __restrict__ AT, const float* __restrict__ src,
                           float* __restrict__ ax0) {
    int m = blockIdx.x;
    int b = m & 31, t = m >> 5;
    __shared__ float ss[NN];
    int tid = threadIdx.x;  // 320
    if (tid < NN) ss[tid] = src[((size_t)b * TT + t) * NN + tid];
    __syncthreads();
    if (tid < NN) {
        float acc = 0.f;
        for (int mm = 0; mm < NN; mm++) acc += AT[(size_t)mm * NN + tid] * ss[mm];
        ax0[(size_t)m * NN + tid] = acc;
    }
}

// ---------------- layer-0 x-contribution ----------------
template <int O>
__global__ void xc0_kernel(const float* __restrict__ src, const float* __restrict__ ax0,
                           const float* __restrict__ Wx, const float* __restrict__ Bv,
                           float* __restrict__ xc) {
    size_t idx = (size_t)blockIdx.x * blockDim.x + threadIdx.x;
    if (idx >= (size_t)MT * NN * O) return;
    int o = (int)(idx % O);
    int n = (int)((idx / O) % NN);
    int m = (int)(idx / ((size_t)O * NN));
    int b = m & 31, t = m >> 5;
    float s = src[((size_t)b * TT + t) * NN + n];
    float a = ax0[(size_t)m * NN + n];
    xc[idx] = s * Wx[((size_t)n * 2) * O + o] + a * Wx[((size_t)n * 2 + 1) * O + o]
            + Bv[(size_t)n * O + o];
}

// ---------------- t=0 specialized step ----------------
__global__ void step0_kernel(const float* __restrict__ XCG, const float* __restrict__ XCU,
                             float* __restrict__ H, float* __restrict__ HS) {
    int idx = blockIdx.x * blockDim.x + threadIdx.x;
    if (idx >= BB * NN * 64) return;
    int ib = idx >> 6, o = idx & 63;
    float r = fsig(XCG[(size_t)ib * 128 + 64 + o]);
    float hc = ftanh(XCU[idx]);
    float h = (1.f - r) * hc;
    H[idx] = h;
    HS[idx] = h;
}

// ---------------- batched A @ V with f32x2 + prefetch + coalesced AT ----------------
// OUT[bb][n][c] = sum_m A[n][m] V[bb][m][c] ;  A[n][m] = AT[m*NN+n]
__global__ void __launch_bounds__(256) av_kernel(
        const float* __restrict__ AT, const float* __restrict__ V,
        float* __restrict__ OUT) {
    int n0 = blockIdx.x * 32, bb = blockIdx.y;
    const float* Vb = V + (size_t)bb * NN * 64;
    float* Ob = OUT + (size_t)bb * NN * 64;
    __shared__ float vs[32][64];
    __shared__ float as_[32][34];  // [mm][n-local], rows 8B-aligned
    int tid = threadIdx.x, tx = tid & 31, ty = tid >> 5;
    ull acc[2][2] = {{0ull, 0ull}, {0ull, 0ull}};
    float4 vreg[2]; float areg[4];
    auto ldtile = [&](int m0, float4 vr[2], float ar[4]) {
#pragma unroll
        for (int s = 0; s < 2; s++) {
            int q = tid + s * 256;
            int mm = q >> 4, c4 = (q & 15) * 4;
            int m = m0 + mm;
            vr[s] = (m < NN) ? *reinterpret_cast<const float4*>(&Vb[(size_t)m * 64 + c4])
                             : make_float4(0.f, 0.f, 0.f, 0.f);
        }
#pragma unroll
        for (int s = 0; s < 4; s++) {
            int i = tid + s * 256;
            int mm = i >> 5, j = i & 31;            // lanes -> consecutive j (coalesced)
            int m = m0 + mm, n2 = n0 + j;
            ar[s] = (m < NN && n2 < NN) ? AT[(size_t)m * NN + n2] : 0.f;
        }
    };
    ldtile(0, vreg, areg);
#pragma unroll 1
    for (int t = 0; t < 10; t++) {
        if (t) __syncthreads();
#pragma unroll
        for (int s = 0; s < 2; s++) {
            int q = tid + s * 256;
            *reinterpret_cast<float4*>(&vs[q >> 4][(q & 15) * 4]) = vreg[s];
        }
#pragma unroll
        for (int s = 0; s < 4; s++) {
            int i = tid + s * 256;
            as_[i >> 5][i & 31] = areg[s];
        }
        __syncthreads();
        if (t < 9) ldtile((t + 1) * 32, vreg, areg);
#pragma unroll
        for (int mm = 0; mm < 32; mm++) {
            ull a01 = *reinterpret_cast<const ull*>(&as_[mm][4 * ty]);
            ull a23 = *reinterpret_cast<const ull*>(&as_[mm][4 * ty + 2]);
            ull v0 = pk2(vs[mm][tx]);
            ull v1 = pk2(vs[mm][tx + 32]);
            ffma2(acc[0][0], a01, v0);
            ffma2(acc[1][0], a23, v0);
            ffma2(acc[0][1], a01, v1);
            ffma2(acc[1][1], a23, v1);
        }
    }
    int nb = n0 + 4 * ty;
    float o00, o01, o10, o11, o20, o21, o30, o31;
    unpk(acc[0][0], o00, o10);
    unpk(acc[1][0], o20, o30);
    unpk(acc[0][1], o01, o11);
    unpk(acc[1][1], o21, o31);
    if (nb < NN)     { Ob[(size_t)nb * 64 + tx] = o00;       Ob[(size_t)nb * 64 + tx + 32] = o01; }
    if (nb + 1 < NN) { Ob[(size_t)(nb+1) * 64 + tx] = o10;   Ob[(size_t)(nb+1) * 64 + tx + 32] = o11; }
    if (nb + 2 < NN) { Ob[(size_t)(nb+2) * 64 + tx] = o20;   Ob[(size_t)(nb+2) * 64 + tx + 32] = o21; }
    if (nb + 3 < NN) { Ob[(size_t)(nb+3) * 64 + tx] = o30;   Ob[(size_t)(nb+3) * 64 + tx + 32] = o31; }
}

// ---------------- per-node GEMM, f32x2 col-pairs + W prefetch ----------------
// MODE 0: C = acc + AX[n][o]
// MODE 1: v=sigmoid(acc+AX[ib]); o<64 -> C2=v*HOLD ; o>=64 -> C=v
// MODE 2: hc=tanh(acc+AX[ib]); hn=RB*HOLD+(1-RB)*hc -> C and C2
template <int O, int MODE>
__global__ void __launch_bounds__(256) node_gemm(
        const float* __restrict__ X1, const float* __restrict__ X2,
        const float* __restrict__ W, const float* __restrict__ AX,
        const float* __restrict__ RB, const float* __restrict__ HOLD,
        float* __restrict__ C, float* __restrict__ C2) {
    constexpr int NP = O / 64;
    constexpr int WV = O / 32;
    int n = blockIdx.x, m0 = blockIdx.y * 32;
    __shared__ float xs[32][128];
    __shared__ float ws[32][O];
    int tid = threadIdx.x, tx = tid & 31, ty = tid >> 5;
#pragma unroll
    for (int s = 0; s < 4; s++) {
        int q = tid + s * 256;
        int m = q >> 5, j4 = (q & 31) * 4;
        const float* sp = (j4 < 64) ? X1 : X2;
        float4 v = *reinterpret_cast<const float4*>(
            &sp[((size_t)(m0 + m) * NN + n) * 64 + (j4 & 63)]);
        *reinterpret_cast<float4*>(&xs[m][j4]) = v;
    }
    const float* Wn = W + (size_t)n * 128 * O;
    float4 wst[WV];
#pragma unroll
    for (int s = 0; s < WV; s++)
        wst[s] = reinterpret_cast<const float4*>(Wn)[tid + s * 256];
    ull acc[4][NP];
#pragma unroll
    for (int r = 0; r < 4; r++)
#pragma unroll
        for (int p = 0; p < NP; p++) acc[r][p] = 0ull;
#pragma unroll 1
    for (int k0 = 0; k0 < 4; k0++) {
        if (k0) __syncthreads();
#pragma unroll
        for (int s = 0; s < WV; s++)
            reinterpret_cast<float4*>(ws)[tid + s * 256] = wst[s];
        __syncthreads();
        if (k0 < 3) {
            const float4* Wt = reinterpret_cast<const float4*>(Wn + (size_t)(k0 + 1) * 32 * O);
#pragma unroll
            for (int s = 0; s < WV; s++) wst[s] = Wt[tid + s * 256];
        }
#pragma unroll
        for (int kk = 0; kk < 32; kk++) {
            ull wp[NP];
#pragma unroll
            for (int p = 0; p < NP; p++)
                wp[p] = *reinterpret_cast<const ull*>(&ws[kk][2 * tx + 64 * p]);
#pragma unroll
            for (int r = 0; r < 4; r++) {
                ull xp = pk2(xs[ty + 8 * r][k0 * 32 + kk]);
#pragma unroll
                for (int p = 0; p < NP; p++) ffma2(acc[r][p], xp, wp[p]);
            }
        }
    }
#pragma unroll
    for (int r = 0; r < 4; r++) {
        int m = m0 + ty + 8 * r;
        size_t ib = (size_t)m * NN + n;
#pragma unroll
        for (int p = 0; p < NP; p++) {
            float v0, v1;
            unpk(acc[r][p], v0, v1);
            int o0 = 2 * tx + 64 * p;
            if (MODE == 0) {
                C[ib * O + o0]     = v0 + AX[(size_t)n * O + o0];
                C[ib * O + o0 + 1] = v1 + AX[(size_t)n * O + o0 + 1];
            } else if (MODE == 1) {
                float s0 = fsig(v0 + AX[ib * O + o0]);
                float s1 = fsig(v1 + AX[ib * O + o0 + 1]);
                if (p == 0) {
                    C2[ib * 64 + o0]     = s0 * HOLD[ib * 64 + o0];
                    C2[ib * 64 + o0 + 1] = s1 * HOLD[ib * 64 + o0 + 1];
                } else {
                    C[ib * 64 + o0 - 64] = s0;
                    C[ib * 64 + o0 - 63] = s1;
                }
            } else {
                float hc0 = ftanh(v0 + AX[ib * O + o0]);
                float hc1 = ftanh(v1 + AX[ib * O + o0 + 1]);
                float r0 = RB[ib * 64 + o0], r1 = RB[ib * 64 + o0 + 1];
                float hd0 = HOLD[ib * 64 + o0], hd1 = HOLD[ib * 64 + o0 + 1];
                float h0 = r0 * hd0 + (1.f - r0) * hc0;
                float h1 = r1 * hd1 + (1.f - r1) * hc1;
                C[ib * 64 + o0] = h0;  C[ib * 64 + o0 + 1] = h1;
                if (C2) { C2[ib * 64 + o0] = h0; C2[ib * 64 + o0 + 1] = h1; }
            }
        }
    }
}

// ---------------- attention tables ----------------
__global__ void attn_prep(const float* __restrict__ mw, const float* __restrict__ mb,
                          const float* __restrict__ wq, const float* __restrict__ bq,
                          const float* __restrict__ wk, const float* __restrict__ bk,
                          const float* __restrict__ wv, const float* __restrict__ bv,
                          float* __restrict__ tbl) {
    __shared__ float MQ[64], MK[64], CQ11[64], CK[12][64], CT[12][64];
    int o = threadIdx.x;  // 64 threads
    for (int t = 0; t < 12; t++) {
        int p = o >> 1;
        float ang = (float)t * powf(10000.f, -(float)(2 * p) / 64.f);
        CT[t][o] = mb[o] + ((o & 1) ? cosf(ang) : sinf(ang));
    }
    __syncthreads();
    float mq = 0.f, mk = 0.f, mv = 0.f;
    for (int i = 0; i < 64; i++) {
        float w = mw[i];
        mq += w * wq[i * 64 + o];
        mk += w * wk[i * 64 + o];
        mv += w * wv[i * 64 + o];
    }
    MQ[o] = mq; MK[o] = mk;
    tbl[o] = mv;
    tbl[64 + o] = CT[11][o];
    float cq = bq[o];
    for (int i = 0; i < 64; i++) cq += CT[11][i] * wq[i * 64 + o];
    CQ11[o] = cq;
    for (int t = 0; t < 12; t++) {
        float ck = bk[o], cv = bv[o];
        for (int i = 0; i < 64; i++) {
            float c = CT[t][i];
            ck += c * wk[i * 64 + o];
            cv += c * wv[i * 64 + o];
        }
        CK[t][o] = ck;
        tbl[128 + t * 64 + o] = cv;
    }
    __syncthreads();
    if (o < 4) {
        float a = 0.f, c = 0.f;
        for (int d = 0; d < 16; d++) {
            a += MQ[o * 16 + d] * MK[o * 16 + d];
            c += CQ11[o * 16 + d] * MK[o * 16 + d];
        }
        tbl[896 + o] = a;
        tbl[900 + o] = c;
    }
    if (o < 48) {
        int h = o / 12, s = o % 12;
        float b = 0.f, dd = 0.f;
        for (int d = 0; d < 16; d++) {
            b  += MQ[h * 16 + d] * CK[s][h * 16 + d];
            dd += CQ11[h * 16 + d] * CK[s][h * 16 + d];
        }
        tbl[904 + o] = b;
        tbl[952 + o] = dd;
    }
}

// ---------------- attention + wo + LN1 ----------------
__global__ void attn_main(const float* __restrict__ src, const float* __restrict__ mw,
                          const float* __restrict__ wo, const float* __restrict__ bo,
                          const float* __restrict__ g1, const float* __restrict__ b1,
                          const float* __restrict__ tblg, float* __restrict__ O1) {
    __shared__ float tbl[1000];
    __shared__ float wos[4096];
    __shared__ float ovs[64][65];
    int tid = threadIdx.x;
    for (int i = tid; i < 1000; i += 256) tbl[i] = tblg[i];
    for (int i = tid; i < 4096; i += 256) wos[i] = wo[i];
    __syncthreads();
    int g = tid >> 2, hq = tid & 3;
    int bn = blockIdx.x * 64 + g;
    bool act = bn < BN;
    int b = act ? bn / NN : 0;
    int n = act ? bn % NN : 0;
    float sv[12];
    for (int s = 0; s < 12; s++) sv[s] = src[((size_t)b * TT + s) * NN + n];
    float sT = sv[11];
    const float* Ah = tbl + 896;
    const float* Ch = tbl + 900;
    const float* Bh = tbl + 904;
    const float* Dh = tbl + 952;
    float sc[12], smax = -1e30f;
    for (int s = 0; s < 12; s++) {
        float v = 0.25f * (sT * sv[s] * Ah[hq] + sT * Bh[hq * 12 + s]
                           + sv[s] * Ch[hq] + Dh[hq * 12 + s]);
        sc[s] = v;
        smax = fmaxf(smax, v);
    }
    float ssum = 0.f;
    for (int s = 0; s < 12; s++) { sc[s] = __expf(sc[s] - smax); ssum += sc[s]; }
    float inv = __fdividef(1.f, ssum), sa = 0.f;
    for (int s = 0; s < 12; s++) { sc[s] *= inv; sa += sc[s] * sv[s]; }
    for (int d = 0; d < 16; d++) {
        int dg = hq * 16 + d;
        float ov = sa * tbl[dg];
        for (int s = 0; s < 12; s++) ov += sc[s] * tbl[128 + s * 64 + dg];
        ovs[g][dg] = ov;
    }
    __syncthreads();
    float u[16], lsum = 0.f, lsq = 0.f;
    for (int d = 0; d < 16; d++) {
        int o = hq * 16 + d;
        float acc = bo[o];
        for (int i = 0; i < 64; i++) acc += ovs[g][i] * wos[i * 64 + o];
        float uu = sT * mw[o] + tbl[64 + o] + acc;
        u[d] = uu;
        lsum += uu;
        lsq += uu * uu;
    }
    lsum += __shfl_xor_sync(~0u, lsum, 1); lsum += __shfl_xor_sync(~0u, lsum, 2);
    lsq  += __shfl_xor_sync(~0u, lsq, 1);  lsq  += __shfl_xor_sync(~0u, lsq, 2);
    float mean = lsum / 64.f, var = lsq / 64.f - mean * mean;
    float rs = rsqrtf(var + 1e-5f);
    if (act)
        for (int d = 0; d < 16; d++) {
            int o = hq * 16 + d;
            O1[(size_t)bn * 64 + o] = (u[d] - mean) * rs * g1[o] + b1[o];
        }
}

// ---------------- FFN + LN2 + combine + conv ----------------
__global__ void __launch_bounds__(256) ffn_kernel(
        const float* __restrict__ O1, const float* __restrict__ W1,
        const float* __restrict__ B1f, const float* __restrict__ W2,
        const float* __restrict__ B2f, const float* __restrict__ g2,
        const float* __restrict__ b2l, const float* __restrict__ HL,
        const float* __restrict__ wsp, const float* __restrict__ wtp,
        const float* __restrict__ cw, const float* __restrict__ cb,
        float* __restrict__ OUT) {
    __shared__ float xs[32][64];
    __shared__ float w1t[64][32];
    __shared__ float ht[32][33];
    __shared__ float w2t[32][64];
    int tid = threadIdx.x, tx = tid & 31, ty = tid >> 5;
    int m0 = blockIdx.x * 32;
    for (int i = tid; i < 2048; i += 256) {
        int a = i >> 6, c = i & 63;
        xs[a][c] = O1[(size_t)(m0 + a) * 64 + c];
    }
    ull acc[4] = {0ull, 0ull, 0ull, 0ull};
#pragma unroll 1
    for (int j0 = 0; j0 < 1024; j0 += 32) {
        __syncthreads();
        for (int i = tid; i < 2048; i += 256)
            w1t[i >> 5][i & 31] = W1[(size_t)(i >> 5) * 1024 + j0 + (i & 31)];
        for (int i = tid; i < 2048; i += 256)
            w2t[i >> 6][i & 63] = W2[(size_t)(j0 + (i >> 6)) * 64 + (i & 63)];
        __syncthreads();
#pragma unroll
        for (int rep = 0; rep < 2; rep++) {
            int slot = tid + rep * 256;
            int a = slot >> 4, bp = (slot & 15) * 2;
            ull h = pk(B1f[j0 + bp], B1f[j0 + bp + 1]);
#pragma unroll
            for (int k = 0; k < 64; k++)
                ffma2(h, pk2(xs[a][k]),
                      *reinterpret_cast<const ull*>(&w1t[k][bp]));
            float h0, h1;
            unpk(h, h0, h1);
            ht[a][bp]     = fmaxf(h0, 0.f);
            ht[a][bp + 1] = fmaxf(h1, 0.f);
        }
        __syncthreads();
#pragma unroll
        for (int jj = 0; jj < 32; jj++) {
            ull w = *reinterpret_cast<const ull*>(&w2t[jj][2 * tx]);
#pragma unroll
            for (int r = 0; r < 4; r++)
                ffma2(acc[r], pk2(ht[ty + 8 * r][jj]), w);
        }
    }
#pragma unroll
    for (int r = 0; r < 4; r++) {
        int row = m0 + ty + 8 * r;
        int b = row / NN, n = row % NN;
        float a0, a1;
        unpk(acc[r], a0, a1);
        int o0 = 2 * tx, o1 = 2 * tx + 1;
        float u0 = xs[ty + 8 * r][o0] + a0 + B2f[o0];
        float u1 = xs[ty + 8 * r][o1] + a1 + B2f[o1];
        float s = u0 + u1, q = u0 * u0 + u1 * u1;
        for (int off = 16; off; off >>= 1) {
            s += __shfl_xor_sync(~0u, s, off);
            q += __shfl_xor_sync(~0u, q, off);
        }
        float mean = s / 64.f, var = q / 64.f - mean * mean;
        float rs = rsqrtf(var + 1e-5f);
        float o20 = (u0 - mean) * rs * g2[o0] + b2l[o0];
        float o21 = (u1 - mean) * rs * g2[o1] + b2l[o1];
        size_t hb = (size_t)row * 64;
        float c0 = HL[hb + o0] * wsp[(size_t)n * 64 + o0] + o20 * wtp[(size_t)n * 64 + o0];
        float c1 = HL[hb + o1] * wsp[(size_t)n * 64 + o1] + o21 * wtp[(size_t)n * 64 + o1];
        for (int to = 0; to < 12; to++) {
            float p = c0 * cw[to * 64 + o0] + c1 * cw[to * 64 + o1];
            for (int off = 16; off; off >>= 1) p += __shfl_xor_sync(~0u, p, off);
            if (tx == 0) OUT[((size_t)b * 12 + to) * NN + n] = p + cb[to];
        }
    }
}

// ---------------- launch ----------------
extern "C" void kernel_launch(void* const* d_in, const int* in_sizes, int n_in,
                              void* d_out, int out_size) {
    const float* src  = (const float*)d_in[0];
    const float* ne   = (const float*)d_in[1];
    const float* gw0  = (const float*)d_in[2];
    const float* gb0  = (const float*)d_in[3];
    const float* uw0  = (const float*)d_in[4];
    const float* ub0  = (const float*)d_in[5];
    const float* gw1  = (const float*)d_in[6];
    const float* gb1  = (const float*)d_in[7];
    const float* uw1  = (const float*)d_in[8];
    const float* ub1  = (const float*)d_in[9];
    const float* mlpw = (const float*)d_in[10];
    const float* mlpb = (const float*)d_in[11];
    const float* wq = (const float*)d_in[12]; const float* bq = (const float*)d_in[13];
    const float* wk = (const float*)d_in[14]; const float* bk = (const float*)d_in[15];
    const float* wv = (const float*)d_in[16]; const float* bv = (const float*)d_in[17];
    const float* wo = (const float*)d_in[18]; const float* bo = (const float*)d_in[19];
    const float* fw1 = (const float*)d_in[20]; const float* fb1 = (const float*)d_in[21];
    const float* fw2 = (const float*)d_in[22]; const float* fb2 = (const float*)d_in[23];
    const float* l1g = (const float*)d_in[24]; const float* l1b = (const float*)d_in[25];
    const float* l2g = (const float*)d_in[26]; const float* l2b = (const float*)d_in[27];
    const float* wsp = (const float*)d_in[28]; const float* wtp = (const float*)d_in[29];
    const float* cw  = (const float*)d_in[30]; const float* cb  = (const float*)d_in[31];
    float* out = (float*)d_out;

    float* G;
    cudaGetSymbolAddress((void**)&G, g_mem);
    float* A    = G + O_A;    float* ATr  = G + O_ATR;
    float* WHG0 = G + O_WHG0; float* WHU0 = G + O_WHU0;
    float* WXG0 = G + O_WXG0; float* WXU0 = G + O_WXU0;
    float* WHG1 = G + O_WHG1; float* WHU1 = G + O_WHU1;
    float* WXG1 = G + O_WXG1; float* WXU1 = G + O_WXU1;
    float* BG0  = G + O_BG0;  float* BU0  = G + O_BU0;
    float* BG1  = G + O_BG1;  float* BU1  = G + O_BU1;
    float* AX0  = G + O_AX0;
    float* XCG0 = G + O_XCG0; float* XCU0 = G + O_XCU0;
    float* XCG1 = G + O_XCG1; float* XCU1 = G + O_XCU1;
    float* HS0  = G + O_HS0;  float* AX1  = G + O_AX1;
    float* H    = G + O_H;    float* AH   = G + O_AH;
    float* ZH   = G + O_ZH;   float* AZH  = G + O_AZH;
    float* R    = G + O_R;    float* O1   = G + O_O1;
    float* TBL  = G + O_TBL;

    adj_kernel<<<NN, 128>>>(ne, A, ATr);

    auto blocks = [](int total) { return (total + 255) / 256; };
    int tWH = NN * 128 * 128, tWU = NN * 128 * 64;
    wmix_kernel<<<blocks(tWH), 256>>>(ne, gw0, WHG0, 128, 128, 65, 1, 64, tWH);
    wmix_kernel<<<blocks(tWU), 256>>>(ne, uw0, WHU0, 128, 64, 65, 1, 64, tWU);
    wmix_kernel<<<blocks(NN * 2 * 128), 256>>>(ne, gw0, WXG0, 2, 128, 65, 0, 1, NN * 2 * 128);
    wmix_kernel<<<blocks(NN * 2 * 64), 256>>>(ne, uw0, WXU0, 2, 64, 65, 0, 1, NN * 2 * 64);
    wmix_kernel<<<blocks(tWH), 256>>>(ne, gw1, WHG1, 128, 128, 128, 64, 64, tWH);
    wmix_kernel<<<blocks(tWU), 256>>>(ne, uw1, WHU1, 128, 64, 128, 64, 64, tWU);
    wmix_kernel<<<blocks(tWH), 256>>>(ne, gw1, WXG1, 128, 128, 128, 0, 64, tWH);
    wmix_kernel<<<blocks(tWU), 256>>>(ne, uw1, WXU1, 128, 64, 128, 0, 64, tWU);
    bmix_kernel<<<blocks(NN * 128), 256>>>(ne, gb0, BG0, 128, NN * 128);
    bmix_kernel<<<blocks(NN * 64), 256>>>(ne, ub0, BU0, 64, NN * 64);
    bmix_kernel<<<blocks(NN * 128), 256>>>(ne, gb1, BG1, 128, NN * 128);
    bmix_kernel<<<blocks(NN * 64), 256>>>(ne, ub1, BU1, 64, NN * 64);

    ax0_kernel<<<MT, 320>>>(ATr, src, AX0);
    xc0_kernel<128><<<blocks(MT * NN * 128), 256>>>(src, AX0, WXG0, BG0, XCG0);
    xc0_kernel<64><<<blocks(MT * NN * 64), 256>>>(src, AX0, WXU0, BU0, XCU0);

    int hbN = BB * NN * 64;
    // ---- layer 0 ----
    step0_kernel<<<blocks(hbN), 256>>>(XCG0, XCU0, H, HS0);
    for (int t = 1; t < TT; t++) {
        av_kernel<<<dim3(10, BB), 256>>>(ATr, H, AH);
        node_gemm<128, 1><<<dim3(NN, 1), 256>>>(H, AH, WHG0,
            XCG0 + (size_t)t * BB * NN * 128, nullptr, H, R, ZH);
        av_kernel<<<dim3(10, BB), 256>>>(ATr, ZH, AZH);
        node_gemm<64, 2><<<dim3(NN, 1), 256>>>(ZH, AZH, WHU0,
            XCU0 + (size_t)t * BB * NN * 64, R, H, H, HS0 + (size_t)t * BB * NN * 64);
    }

    // ---- layer-1 x-contributions (parallel over all t) ----
    av_kernel<<<dim3(10, MT), 256>>>(ATr, HS0, AX1);
    node_gemm<128, 0><<<dim3(NN, 12), 256>>>(HS0, AX1, WXG1, BG1, nullptr, nullptr, XCG1, nullptr);
    node_gemm<64, 0><<<dim3(NN, 12), 256>>>(HS0, AX1, WXU1, BU1, nullptr, nullptr, XCU1, nullptr);

    // ---- layer 1 ----
    step0_kernel<<<blocks(hbN), 256>>>(XCG1, XCU1, H, H);
    for (int t = 1; t < TT; t++) {
        av_kernel<<<dim3(10, BB), 256>>>(ATr, H, AH);
        node_gemm<128, 1><<<dim3(NN, 1), 256>>>(H, AH, WHG1,
            XCG1 + (size_t)t * BB * NN * 128, nullptr, H, R, ZH);
        av_kernel<<<dim3(10, BB), 256>>>(ATr, ZH, AZH);
        node_gemm<64, 2><<<dim3(NN, 1), 256>>>(ZH, AZH, WHU1,
            XCU1 + (size_t)t * BB * NN * 64, R, H, H, H);
    }

    attn_prep<<<1, 64>>>(mlpw, mlpb, wq, bq, wk, bk, wv, bv, TBL);
    attn_main<<<(BN + 63) / 64, 256>>>(src, mlpw, wo, bo, l1g, l1b, TBL, O1);
    ffn_kernel<<<NN, 256>>>(O1, fw1, fb1, fw2, fb2, l2g, l2b, H, wsp, wtp, cw, cb, out);
}